// round 2
// baseline (speedup 1.0000x reference)
#include <cuda_runtime.h>
#include <math.h>

#define NB   8
#define CIN  128
#define CB   64
#define NPOS 4096
#define SK   68   // smem row stride for 64-wide tiles (float4-aligned, 4-bank skew)

// Scratch (no allocs allowed): theta/phi/g/y in [b][n][k] layout, k contiguous.
__device__ float g_q[NB * NPOS * CB];
__device__ float g_kk[NB * NPOS * CB];
__device__ float g_v[NB * NPOS * CB];
__device__ float g_y[NB * NPOS * CB];

// ---------------------------------------------------------------------------
// Kernel 1: theta/phi/g = W @ x   (per batch: [64,128] x [128,4096])
// CTA = (batch b, 64 positions). Output transposed to [b][n][k].
// ---------------------------------------------------------------------------
__global__ void __launch_bounds__(256) proj_kernel(
    const float* __restrict__ x, const float* __restrict__ wt,
    const float* __restrict__ wp, const float* __restrict__ wg)
{
    extern __shared__ float sm[];
    float* xs = sm;               // [128][64]   xs[c][n]
    float* ws = sm + CIN * 64;    // 3 x [128][65], transposed: ws[c][k]
    const int b  = blockIdx.y;
    const int n0 = blockIdx.x * 64;
    const int tid = threadIdx.x;

    for (int i = tid; i < CIN * 64; i += 256) {
        int c = i >> 6, j = i & 63;
        xs[i] = x[(b * CIN + c) * NPOS + n0 + j];
    }
    for (int i = tid; i < CB * CIN; i += 256) {
        int k = i >> 7, c = i & 127;
        ws[c * 65 + k]               = wt[i];
        ws[CIN * 65 + c * 65 + k]    = wp[i];
        ws[2 * CIN * 65 + c * 65 + k] = wg[i];
    }
    __syncthreads();

    const int k  = tid & 63;
    const int nb = (tid >> 6) * 16;     // 16 contiguous positions per thread
    float at[16], ap[16], ag[16];
#pragma unroll
    for (int i = 0; i < 16; i++) { at[i] = 0.f; ap[i] = 0.f; ag[i] = 0.f; }

    for (int c = 0; c < CIN; c++) {
        float w0 = ws[c * 65 + k];
        float w1 = ws[CIN * 65 + c * 65 + k];
        float w2 = ws[2 * CIN * 65 + c * 65 + k];
        const float4* xr = (const float4*)(xs + c * 64 + nb);
#pragma unroll
        for (int q = 0; q < 4; q++) {
            float4 xv = xr[q];
            at[4*q+0] += w0 * xv.x; at[4*q+1] += w0 * xv.y;
            at[4*q+2] += w0 * xv.z; at[4*q+3] += w0 * xv.w;
            ap[4*q+0] += w1 * xv.x; ap[4*q+1] += w1 * xv.y;
            ap[4*q+2] += w1 * xv.z; ap[4*q+3] += w1 * xv.w;
            ag[4*q+0] += w2 * xv.x; ag[4*q+1] += w2 * xv.y;
            ag[4*q+2] += w2 * xv.z; ag[4*q+3] += w2 * xv.w;
        }
    }
#pragma unroll
    for (int i = 0; i < 16; i++) {
        int o = (b * NPOS + n0 + nb + i) * CB + k;
        g_q[o]  = at[i];
        g_kk[o] = ap[i];
        g_v[o]  = ag[i];
    }
}

// ---------------------------------------------------------------------------
// Kernel 2: flash attention. Q=theta^T, K=phi^T, V=g^T. No logit scaling.
// CTA = (batch, 64 query rows). 256 threads as 16x16, 4x4 micro-tiles.
// ---------------------------------------------------------------------------
__global__ void __launch_bounds__(256) attn_kernel()
{
    extern __shared__ float sm[];
    float* Qs = sm;               // [64 d][SK]  Qs[d][i]   (d-major for float4 frags)
    float* Ks = Qs + 64 * SK;     // [64 d][SK]  Ks[d][j]
    float* Vs = Ks + 64 * SK;     // [64 j][SK]  Vs[j][d]
    float* Ps = Vs + 64 * SK;     // [64 j][SK]  Ps[j][i]
    const int b  = blockIdx.y;
    const int n0 = blockIdx.x * 64;
    const int tid = threadIdx.x;
    const int tx = tid & 15, ty = tid >> 4;

    const float* qg = g_q + (b * NPOS + n0) * CB;
    for (int idx = tid; idx < 64 * 64; idx += 256) {
        int i = idx >> 6, k = idx & 63;
        Qs[k * SK + i] = qg[idx];           // transpose on load
    }

    float m_i[4], l_i[4], acc[4][4];
#pragma unroll
    for (int r = 0; r < 4; r++) {
        m_i[r] = -INFINITY; l_i[r] = 0.f;
#pragma unroll
        for (int c = 0; c < 4; c++) acc[r][c] = 0.f;
    }

    for (int kb = 0; kb < NPOS / 64; kb++) {
        __syncthreads();   // prev iter's S/PV done reading Ks/Vs/Ps
        const float* kg = g_kk + (b * NPOS + kb * 64) * CB;
        const float* vg = g_v  + (b * NPOS + kb * 64) * CB;
        for (int idx = tid; idx < 64 * 64; idx += 256) {
            int j = idx >> 6, k = idx & 63;
            Ks[k * SK + j] = kg[idx];       // transpose
            Vs[j * SK + k] = vg[idx];       // direct
        }
        __syncthreads();

        // S = Q^T K   (s[r][c]: query row ty*4+r, key col tx*4+c)
        float s[4][4];
#pragma unroll
        for (int r = 0; r < 4; r++)
#pragma unroll
            for (int c = 0; c < 4; c++) s[r][c] = 0.f;

#pragma unroll 8
        for (int d = 0; d < 64; d++) {
            float4 qf = *(const float4*)(Qs + d * SK + ty * 4);
            float4 kf = *(const float4*)(Ks + d * SK + tx * 4);
            float qr[4] = {qf.x, qf.y, qf.z, qf.w};
            float kc[4] = {kf.x, kf.y, kf.z, kf.w};
#pragma unroll
            for (int r = 0; r < 4; r++)
#pragma unroll
                for (int c = 0; c < 4; c++) s[r][c] += qr[r] * kc[c];
        }

        // online softmax over the 16 tx lanes covering each row
#pragma unroll
        for (int r = 0; r < 4; r++) {
            float mx = fmaxf(fmaxf(s[r][0], s[r][1]), fmaxf(s[r][2], s[r][3]));
#pragma unroll
            for (int off = 8; off >= 1; off >>= 1)
                mx = fmaxf(mx, __shfl_xor_sync(0xffffffffu, mx, off));
            float mnew  = fmaxf(m_i[r], mx);
            float scale = __expf(m_i[r] - mnew);
            float rs = 0.f;
#pragma unroll
            for (int c = 0; c < 4; c++) {
                s[r][c] = __expf(s[r][c] - mnew);
                rs += s[r][c];
            }
#pragma unroll
            for (int off = 8; off >= 1; off >>= 1)
                rs += __shfl_xor_sync(0xffffffffu, rs, off);
            l_i[r] = l_i[r] * scale + rs;
            m_i[r] = mnew;
#pragma unroll
            for (int c = 0; c < 4; c++) acc[r][c] *= scale;
        }

        // stash P transposed: Ps[j][i]
#pragma unroll
        for (int c = 0; c < 4; c++) {
            float4 pv = make_float4(s[0][c], s[1][c], s[2][c], s[3][c]);
            *(float4*)(Ps + (tx * 4 + c) * SK + ty * 4) = pv;
        }
        __syncthreads();

        // O += P V   (acc[r][c]: query row ty*4+r, out dim tx*4+c)
#pragma unroll 8
        for (int j = 0; j < 64; j++) {
            float4 pf = *(const float4*)(Ps + j * SK + ty * 4);
            float4 vf = *(const float4*)(Vs + j * SK + tx * 4);
            float pr[4] = {pf.x, pf.y, pf.z, pf.w};
            float vc[4] = {vf.x, vf.y, vf.z, vf.w};
#pragma unroll
            for (int r = 0; r < 4; r++)
#pragma unroll
                for (int c = 0; c < 4; c++) acc[r][c] += pr[r] * vc[c];
        }
    }

    float* yg = g_y + (b * NPOS + n0) * CB;
#pragma unroll
    for (int r = 0; r < 4; r++) {
        float inv = 1.f / l_i[r];
        float4 ov = make_float4(acc[r][0] * inv, acc[r][1] * inv,
                                acc[r][2] * inv, acc[r][3] * inv);
        *(float4*)(yg + (ty * 4 + r) * CB + tx * 4) = ov;
    }
}

// ---------------------------------------------------------------------------
// Kernel 3: out = w_last @ y + x
// ---------------------------------------------------------------------------
__global__ void __launch_bounds__(256) out_kernel(
    const float* __restrict__ x, const float* __restrict__ wl,
    float* __restrict__ out)
{
    extern __shared__ float sm[];
    float* ys = sm;               // [64 n][65] : ys[n][k]
    float* ws = ys + 64 * 65;     // [64 k][132]: ws[k][c]
    const int b  = blockIdx.y;
    const int n0 = blockIdx.x * 64;
    const int tid = threadIdx.x;

    const float* yg = g_y + (b * NPOS + n0) * CB;
    for (int idx = tid; idx < 64 * 64; idx += 256) {
        int n = idx >> 6, k = idx & 63;
        ys[n * 65 + k] = yg[idx];
    }
    for (int i = tid; i < CIN * CB; i += 256) {
        int c = i >> 6, k = i & 63;
        ws[k * 132 + c] = wl[i];
    }
    __syncthreads();

    const int n  = tid & 63;
    const int cb = (tid >> 6) * 32;
    float acc[32];
#pragma unroll
    for (int i = 0; i < 32; i++) acc[i] = 0.f;

    for (int k = 0; k < CB; k++) {
        float yv = ys[n * 65 + k];
        const float4* wr = (const float4*)(ws + k * 132 + cb);
#pragma unroll
        for (int q = 0; q < 8; q++) {
            float4 w4 = wr[q];
            acc[4*q+0] += w4.x * yv; acc[4*q+1] += w4.y * yv;
            acc[4*q+2] += w4.z * yv; acc[4*q+3] += w4.w * yv;
        }
    }
#pragma unroll
    for (int i = 0; i < 32; i++) {
        int o = (b * CIN + cb + i) * NPOS + n0 + n;
        out[o] = acc[i] + x[o];
    }
}

// ---------------------------------------------------------------------------
extern "C" void kernel_launch(void* const* d_in, const int* in_sizes, int n_in,
                              void* d_out, int out_size)
{
    const float* x  = (const float*)d_in[0];
    const float* wt = (const float*)d_in[1];
    const float* wp = (const float*)d_in[2];
    const float* wg = (const float*)d_in[3];
    const float* wl = (const float*)d_in[4];
    float* out = (float*)d_out;

    int smem1 = (CIN * 64 + 3 * CIN * 65) * (int)sizeof(float);   // 132,608 B
    int smem2 = 4 * 64 * SK * (int)sizeof(float);                 //  69,632 B
    int smem3 = (64 * 65 + 64 * 132) * (int)sizeof(float);        //  50,432 B
    cudaFuncSetAttribute(proj_kernel, cudaFuncAttributeMaxDynamicSharedMemorySize, smem1);
    cudaFuncSetAttribute(attn_kernel, cudaFuncAttributeMaxDynamicSharedMemorySize, smem2);
    cudaFuncSetAttribute(out_kernel,  cudaFuncAttributeMaxDynamicSharedMemorySize, smem3);

    dim3 grid(NPOS / 64, NB);
    proj_kernel<<<grid, 256, smem1>>>(x, wt, wp, wg);
    attn_kernel<<<grid, 256, smem2>>>();
    out_kernel<<<grid, 256, smem3>>>(x, wl, out);
}

// round 4
// speedup vs baseline: 2.7879x; 2.7879x over previous
#include <cuda_runtime.h>
#include <cuda_fp16.h>
#include <math.h>
#include <stdint.h>

#define NB   8
#define CIN  128
#define CB   64
#define NPOS 4096
#define SH   72   // half-precision smem row stride (even, conflict-free for frag loads)

// Scratch: theta/phi/g/y in [b][n][k] layout, k contiguous.
__device__ float g_q[NB * NPOS * CB];
__device__ float g_kk[NB * NPOS * CB];
__device__ float g_v[NB * NPOS * CB];
__device__ float g_y[NB * NPOS * CB];

// ---------------------------------------------------------------------------
// Kernel 1: theta/phi/g = W @ x   (per batch: [64,128] x [128,4096])
// ---------------------------------------------------------------------------
__global__ void __launch_bounds__(256) proj_kernel(
    const float* __restrict__ x, const float* __restrict__ wt,
    const float* __restrict__ wp, const float* __restrict__ wg)
{
    extern __shared__ float sm[];
    float* xs = sm;               // [128][64]   xs[c][n]
    float* ws = sm + CIN * 64;    // 3 x [128][65], transposed: ws[c][k]
    const int b  = blockIdx.y;
    const int n0 = blockIdx.x * 64;
    const int tid = threadIdx.x;

    for (int i = tid; i < CIN * 64; i += 256) {
        int c = i >> 6, j = i & 63;
        xs[i] = x[(b * CIN + c) * NPOS + n0 + j];
    }
    for (int i = tid; i < CB * CIN; i += 256) {
        int k = i >> 7, c = i & 127;
        ws[c * 65 + k]                = wt[i];
        ws[CIN * 65 + c * 65 + k]     = wp[i];
        ws[2 * CIN * 65 + c * 65 + k] = wg[i];
    }
    __syncthreads();

    const int k  = tid & 63;
    const int nb = (tid >> 6) * 16;
    float at[16], ap[16], ag[16];
#pragma unroll
    for (int i = 0; i < 16; i++) { at[i] = 0.f; ap[i] = 0.f; ag[i] = 0.f; }

    for (int c = 0; c < CIN; c++) {
        float w0 = ws[c * 65 + k];
        float w1 = ws[CIN * 65 + c * 65 + k];
        float w2 = ws[2 * CIN * 65 + c * 65 + k];
        const float4* xr = (const float4*)(xs + c * 64 + nb);
#pragma unroll
        for (int q = 0; q < 4; q++) {
            float4 xv = xr[q];
            at[4*q+0] += w0 * xv.x; at[4*q+1] += w0 * xv.y;
            at[4*q+2] += w0 * xv.z; at[4*q+3] += w0 * xv.w;
            ap[4*q+0] += w1 * xv.x; ap[4*q+1] += w1 * xv.y;
            ap[4*q+2] += w1 * xv.z; ap[4*q+3] += w1 * xv.w;
            ag[4*q+0] += w2 * xv.x; ag[4*q+1] += w2 * xv.y;
            ag[4*q+2] += w2 * xv.z; ag[4*q+3] += w2 * xv.w;
        }
    }
#pragma unroll
    for (int i = 0; i < 16; i++) {
        int o = (b * NPOS + n0 + nb + i) * CB + k;
        g_q[o]  = at[i];
        g_kk[o] = ap[i];
        g_v[o]  = ag[i];
    }
}

// ---------------------------------------------------------------------------
// Kernel 2: flash attention with mma.sync m16n8k16 (fp16 in, fp32 accum).
// S = QK^T via 2-term fp16 split (hi/lo) for near-fp32 logit precision.
// CTA = 64 query rows, 128 threads (4 warps, 16 q-rows each).
// ---------------------------------------------------------------------------
#define MMA16816(C, A0, A1, A2, A3, B0, B1)                                   \
    asm volatile("mma.sync.aligned.m16n8k16.row.col.f32.f16.f16.f32 "         \
                 "{%0,%1,%2,%3}, {%4,%5,%6,%7}, {%8,%9}, {%0,%1,%2,%3};"      \
                 : "+f"(C[0]), "+f"(C[1]), "+f"(C[2]), "+f"(C[3])             \
                 : "r"(A0), "r"(A1), "r"(A2), "r"(A3), "r"(B0), "r"(B1))

__device__ __forceinline__ uint32_t ld_h2(const __half* p) {
    return *(const uint32_t*)p;
}
__device__ __forceinline__ uint32_t pack_h2(float a, float b) {
    __half2 h = __floats2half2_rn(a, b);
    return *(uint32_t*)&h;
}

__global__ void __launch_bounds__(128) attn_kernel()
{
    extern __shared__ __half hsm[];
    __half* Qh = hsm;              // [64 qrow][SH d]
    __half* Ql = Qh + 64 * SH;
    __half* Kh = Ql + 64 * SH;     // [64 j][SH d]
    __half* Kl = Kh + 64 * SH;
    __half* Vt = Kl + 64 * SH;     // [64 d][SH j]  (transposed)
    const int b   = blockIdx.y;
    const int n0  = blockIdx.x * 64;
    const int tid = threadIdx.x;
    const int w    = tid >> 5;
    const int lane = tid & 31;
    const int grp  = lane >> 2;    // groupID (row within fragment)
    const int qd   = lane & 3;     // threadID in group

    // Stage Q, split into hi/lo fp16
    const float* qg = g_q + (b * NPOS + n0) * CB;
    for (int idx = tid; idx < 64 * 64; idx += 128) {
        int r = idx >> 6, c = idx & 63;
        float v = qg[idx];
        __half h = __float2half_rn(v);
        Qh[r * SH + c] = h;
        Ql[r * SH + c] = __float2half_rn(v - __half2float(h));
    }

    float m0 = -INFINITY, m1 = -INFINITY, l0 = 0.f, l1 = 0.f;
    float o[8][4];
#pragma unroll
    for (int dt = 0; dt < 8; dt++)
#pragma unroll
        for (int i = 0; i < 4; i++) o[dt][i] = 0.f;

    for (int kb = 0; kb < NPOS / 64; kb++) {
        __syncthreads();   // previous iteration done with Kh/Kl/Vt (and Q stores visible)
        const float* kg = g_kk + (b * NPOS + kb * 64) * CB;
        const float* vg = g_v  + (b * NPOS + kb * 64) * CB;
        for (int idx = tid; idx < 64 * 64; idx += 128) {
            int r = idx >> 6, c = idx & 63;
            float kv = kg[idx];
            __half h = __float2half_rn(kv);
            Kh[r * SH + c] = h;
            Kl[r * SH + c] = __float2half_rn(kv - __half2float(h));
            Vt[c * SH + r] = __float2half_rn(vg[idx]);
        }
        __syncthreads();

        // ---- S = Q K^T  (16 rows x 64 cols per warp), hi/lo split ----
        float sc[8][4];
#pragma unroll
        for (int nt = 0; nt < 8; nt++)
#pragma unroll
            for (int i = 0; i < 4; i++) sc[nt][i] = 0.f;

#pragma unroll
        for (int ks = 0; ks < 4; ks++) {
            const __half* qp = Qh + (w * 16 + grp) * SH + ks * 16 + 2 * qd;
            const __half* lp = Ql + (w * 16 + grp) * SH + ks * 16 + 2 * qd;
            uint32_t a0 = ld_h2(qp),           a1 = ld_h2(qp + 8 * SH);
            uint32_t a2 = ld_h2(qp + 8),       a3 = ld_h2(qp + 8 * SH + 8);
            uint32_t e0 = ld_h2(lp),           e1 = ld_h2(lp + 8 * SH);
            uint32_t e2 = ld_h2(lp + 8),       e3 = ld_h2(lp + 8 * SH + 8);
#pragma unroll
            for (int nt = 0; nt < 8; nt++) {
                const __half* kp  = Kh + (nt * 8 + grp) * SH + ks * 16 + 2 * qd;
                const __half* klp = Kl + (nt * 8 + grp) * SH + ks * 16 + 2 * qd;
                uint32_t b0 = ld_h2(kp),  b1 = ld_h2(kp + 8);
                uint32_t c0 = ld_h2(klp), c1 = ld_h2(klp + 8);
                MMA16816(sc[nt], a0, a1, a2, a3, b0, b1);   // hi*hi
                MMA16816(sc[nt], a0, a1, a2, a3, c0, c1);   // hi*lo
                MMA16816(sc[nt], e0, e1, e2, e3, b0, b1);   // lo*hi
            }
        }

        // ---- online softmax (row0 = grp row, row1 = grp+8) ----
        float mx0 = -INFINITY, mx1 = -INFINITY;
#pragma unroll
        for (int nt = 0; nt < 8; nt++) {
            mx0 = fmaxf(mx0, fmaxf(sc[nt][0], sc[nt][1]));
            mx1 = fmaxf(mx1, fmaxf(sc[nt][2], sc[nt][3]));
        }
#pragma unroll
        for (int off = 1; off <= 2; off <<= 1) {
            mx0 = fmaxf(mx0, __shfl_xor_sync(0xffffffffu, mx0, off));
            mx1 = fmaxf(mx1, __shfl_xor_sync(0xffffffffu, mx1, off));
        }
        float mn0 = fmaxf(m0, mx0), mn1 = fmaxf(m1, mx1);
        float scl0 = __expf(m0 - mn0), scl1 = __expf(m1 - mn1);
        float rs0 = 0.f, rs1 = 0.f;
#pragma unroll
        for (int nt = 0; nt < 8; nt++) {
            sc[nt][0] = __expf(sc[nt][0] - mn0);
            sc[nt][1] = __expf(sc[nt][1] - mn0);
            sc[nt][2] = __expf(sc[nt][2] - mn1);
            sc[nt][3] = __expf(sc[nt][3] - mn1);
            rs0 += sc[nt][0] + sc[nt][1];
            rs1 += sc[nt][2] + sc[nt][3];
        }
#pragma unroll
        for (int off = 1; off <= 2; off <<= 1) {
            rs0 += __shfl_xor_sync(0xffffffffu, rs0, off);
            rs1 += __shfl_xor_sync(0xffffffffu, rs1, off);
        }
        l0 = l0 * scl0 + rs0;  m0 = mn0;
        l1 = l1 * scl1 + rs1;  m1 = mn1;
#pragma unroll
        for (int dt = 0; dt < 8; dt++) {
            o[dt][0] *= scl0; o[dt][1] *= scl0;
            o[dt][2] *= scl1; o[dt][3] *= scl1;
        }

        // ---- O += P V  (P from registers, V as B operand) ----
#pragma unroll
        for (int kc = 0; kc < 4; kc++) {
            uint32_t a0 = pack_h2(sc[2*kc][0],   sc[2*kc][1]);
            uint32_t a1 = pack_h2(sc[2*kc][2],   sc[2*kc][3]);
            uint32_t a2 = pack_h2(sc[2*kc+1][0], sc[2*kc+1][1]);
            uint32_t a3 = pack_h2(sc[2*kc+1][2], sc[2*kc+1][3]);
#pragma unroll
            for (int dt = 0; dt < 8; dt++) {
                const __half* vp = Vt + (dt * 8 + grp) * SH + kc * 16 + 2 * qd;
                uint32_t b0 = ld_h2(vp), b1 = ld_h2(vp + 8);
                MMA16816(o[dt], a0, a1, a2, a3, b0, b1);
            }
        }
    }

    float inv0 = 1.f / l0, inv1 = 1.f / l1;
    float* yg = g_y + (b * NPOS + n0) * CB;
#pragma unroll
    for (int dt = 0; dt < 8; dt++) {
        int r = w * 16 + grp;
        int d = dt * 8 + 2 * qd;
        *(float2*)&yg[r * CB + d]       = make_float2(o[dt][0] * inv0, o[dt][1] * inv0);
        *(float2*)&yg[(r + 8) * CB + d] = make_float2(o[dt][2] * inv1, o[dt][3] * inv1);
    }
}

// ---------------------------------------------------------------------------
// Kernel 3: out = w_last @ y + x
// ---------------------------------------------------------------------------
__global__ void __launch_bounds__(256) out_kernel(
    const float* __restrict__ x, const float* __restrict__ wl,
    float* __restrict__ out)
{
    extern __shared__ float sm[];
    float* ys = sm;               // [64 n][65] : ys[n][k]
    float* ws = ys + 64 * 65;     // [64 k][132]: ws[k][c]
    const int b  = blockIdx.y;
    const int n0 = blockIdx.x * 64;
    const int tid = threadIdx.x;

    const float* yg = g_y + (b * NPOS + n0) * CB;
    for (int idx = tid; idx < 64 * 64; idx += 256) {
        int n = idx >> 6, k = idx & 63;
        ys[n * 65 + k] = yg[idx];
    }
    for (int i = tid; i < CIN * CB; i += 256) {
        int c = i >> 6, k = i & 63;
        ws[k * 132 + c] = wl[i];
    }
    __syncthreads();

    const int n  = tid & 63;
    const int cb = (tid >> 6) * 32;
    float acc[32];
#pragma unroll
    for (int i = 0; i < 32; i++) acc[i] = 0.f;

    for (int k = 0; k < CB; k++) {
        float yv = ys[n * 65 + k];
        const float4* wr = (const float4*)(ws + k * 132 + cb);
#pragma unroll
        for (int q = 0; q < 8; q++) {
            float4 w4 = wr[q];
            acc[4*q+0] += w4.x * yv; acc[4*q+1] += w4.y * yv;
            acc[4*q+2] += w4.z * yv; acc[4*q+3] += w4.w * yv;
        }
    }
#pragma unroll
    for (int i = 0; i < 32; i++) {
        int o = (b * CIN + cb + i) * NPOS + n0 + n;
        out[o] = acc[i] + x[o];
    }
}

// ---------------------------------------------------------------------------
extern "C" void kernel_launch(void* const* d_in, const int* in_sizes, int n_in,
                              void* d_out, int out_size)
{
    const float* x  = (const float*)d_in[0];
    const float* wt = (const float*)d_in[1];
    const float* wp = (const float*)d_in[2];
    const float* wg = (const float*)d_in[3];
    const float* wl = (const float*)d_in[4];
    float* out = (float*)d_out;

    int smem1 = (CIN * 64 + 3 * CIN * 65) * (int)sizeof(float);   // 132,608 B
    int smem2 = 5 * 64 * SH * (int)sizeof(__half);                //  46,080 B
    int smem3 = (64 * 65 + 64 * 132) * (int)sizeof(float);        //  50,432 B
    cudaFuncSetAttribute(proj_kernel, cudaFuncAttributeMaxDynamicSharedMemorySize, smem1);
    cudaFuncSetAttribute(attn_kernel, cudaFuncAttributeMaxDynamicSharedMemorySize, smem2);
    cudaFuncSetAttribute(out_kernel,  cudaFuncAttributeMaxDynamicSharedMemorySize, smem3);

    dim3 grid(NPOS / 64, NB);
    proj_kernel<<<grid, 256, smem1>>>(x, wt, wp, wg);
    attn_kernel<<<grid, 128, smem2>>>();
    out_kernel<<<grid, 256, smem3>>>(x, wl, out);
}

// round 5
// speedup vs baseline: 3.0484x; 1.0935x over previous
#include <cuda_runtime.h>
#include <cuda_fp16.h>
#include <math.h>
#include <stdint.h>

#define NB   8
#define CIN  128
#define CB   64
#define NPOS 4096
#define SH   72   // half stride for Q/K tiles (conflict-free frag reads)
#define SHV  70   // half stride for Vt (odd word stride: conflict-free transpose stores)

// Scratch: theta/phi/g/y in [b][n][k] layout, k contiguous.
__device__ float g_q[NB * NPOS * CB];
__device__ float g_kk[NB * NPOS * CB];
__device__ float g_v[NB * NPOS * CB];
__device__ float g_y[NB * NPOS * CB];

// ---- packed fp32 pair helpers (FFMA2 path, sm_100+) ------------------------
__device__ __forceinline__ void fma2(unsigned long long& d,
                                     unsigned long long a, unsigned long long b) {
    asm("fma.rn.f32x2 %0, %1, %2, %0;" : "+l"(d) : "l"(a), "l"(b));
}
__device__ __forceinline__ unsigned long long pk2(float lo, float hi) {
    unsigned long long r;
    asm("mov.b64 %0, {%1, %2};" : "=l"(r) : "f"(lo), "f"(hi));
    return r;
}
__device__ __forceinline__ float2 upk2(unsigned long long v) {
    float2 r;
    asm("mov.b64 {%0, %1}, %2;" : "=f"(r.x), "=f"(r.y) : "l"(v));
    return r;
}

// ---------------------------------------------------------------------------
// Kernel 1: theta/phi/g = W @ x.  Weights-only smem (97.5KB -> 2 CTAs/SM),
// x read directly (broadcast LDG.128), FFMA2 accumulation.
// ---------------------------------------------------------------------------
__global__ void __launch_bounds__(256) proj_kernel(
    const float* __restrict__ x, const float* __restrict__ wt,
    const float* __restrict__ wp, const float* __restrict__ wg)
{
    extern __shared__ float ws[];            // 3 x [128 c][65] : ws[c*65+k]
    const int b  = blockIdx.y;
    const int n0 = blockIdx.x * 64;
    const int tid = threadIdx.x;

    for (int i = tid; i < CB * CIN; i += 256) {
        int k = i >> 7, c = i & 127;          // w layout [k][c]
        ws[c * 65 + k]                = wt[i];
        ws[CIN * 65 + c * 65 + k]     = wp[i];
        ws[2 * CIN * 65 + c * 65 + k] = wg[i];
    }
    __syncthreads();

    const int k  = tid & 63;
    const int nb = (tid >> 6) * 16;           // 16 positions -> 8 f32x2 pairs
    unsigned long long at2[8], ap2[8], ag2[8];
#pragma unroll
    for (int i = 0; i < 8; i++) { at2[i] = 0ull; ap2[i] = 0ull; ag2[i] = 0ull; }

    const char* xbase = (const char*)(x + (size_t)b * CIN * NPOS + n0 + nb);
    for (int c = 0; c < CIN; c++) {
        float w0s = ws[c * 65 + k];
        float w1s = ws[CIN * 65 + c * 65 + k];
        float w2s = ws[2 * CIN * 65 + c * 65 + k];
        unsigned long long w0 = pk2(w0s, w0s);
        unsigned long long w1 = pk2(w1s, w1s);
        unsigned long long w2 = pk2(w2s, w2s);
        const double2* xr = (const double2*)(xbase + (size_t)c * NPOS * 4);
#pragma unroll
        for (int q = 0; q < 4; q++) {
            double2 xv = xr[q];
            unsigned long long p0 = __double_as_longlong(xv.x);
            unsigned long long p1 = __double_as_longlong(xv.y);
            fma2(at2[2*q], w0, p0); fma2(at2[2*q+1], w0, p1);
            fma2(ap2[2*q], w1, p0); fma2(ap2[2*q+1], w1, p1);
            fma2(ag2[2*q], w2, p0); fma2(ag2[2*q+1], w2, p1);
        }
    }
#pragma unroll
    for (int j = 0; j < 8; j++) {
        int o = (b * NPOS + n0 + nb + 2 * j) * CB + k;
        float2 t = upk2(at2[j]); g_q[o]  = t.x; g_q[o + CB]  = t.y;
        float2 p = upk2(ap2[j]); g_kk[o] = p.x; g_kk[o + CB] = p.y;
        float2 g = upk2(ag2[j]); g_v[o]  = g.x; g_v[o + CB]  = g.y;
    }
}

// ---------------------------------------------------------------------------
// Kernel 2: flash attention, mma.sync m16n8k16 fp16/fp32, hi/lo logit split.
// CTA = 128 q rows, 128 threads (4 warps x 32 rows = two 16-row A tiles).
// K/V fragments amortized over both tiles; 256 CTAs (halved L2 traffic).
// ---------------------------------------------------------------------------
#define MMA16816(C, A0, A1, A2, A3, B0, B1)                                   \
    asm volatile("mma.sync.aligned.m16n8k16.row.col.f32.f16.f16.f32 "         \
                 "{%0,%1,%2,%3}, {%4,%5,%6,%7}, {%8,%9}, {%0,%1,%2,%3};"      \
                 : "+f"(C[0]), "+f"(C[1]), "+f"(C[2]), "+f"(C[3])             \
                 : "r"(A0), "r"(A1), "r"(A2), "r"(A3), "r"(B0), "r"(B1))

__device__ __forceinline__ uint32_t ld_h2(const __half* p) {
    return *(const uint32_t*)p;
}
__device__ __forceinline__ uint32_t pack_h2(float a, float b) {
    __half2 h = __floats2half2_rn(a, b);
    return *(uint32_t*)&h;
}

__global__ void __launch_bounds__(128, 2) attn_kernel()
{
    extern __shared__ __half hsm[];
    __half* Qh = hsm;               // [128 qrow][SH d]
    __half* Ql = Qh + 128 * SH;
    __half* Kh = Ql + 128 * SH;     // [64 j][SH d]
    __half* Kl = Kh + 64 * SH;
    __half* Vt = Kl + 64 * SH;      // [64 d][SHV j]
    const int b   = blockIdx.y;
    const int n0  = blockIdx.x * 128;
    const int tid = threadIdx.x;
    const int w    = tid >> 5;
    const int lane = tid & 31;
    const int grp  = lane >> 2;
    const int qd   = lane & 3;

    // Stage Q (128 rows), hi/lo split
    const float* qg = g_q + (size_t)(b * NPOS + n0) * CB;
    for (int idx = tid; idx < 128 * 64; idx += 128) {
        int r = idx >> 6, c = idx & 63;
        float v = qg[idx];
        __half h = __float2half_rn(v);
        Qh[r * SH + c] = h;
        Ql[r * SH + c] = __float2half_rn(v - __half2float(h));
    }

    float m01[2][2], l01[2][2];
#pragma unroll
    for (int h = 0; h < 2; h++) {
        m01[h][0] = m01[h][1] = -INFINITY;
        l01[h][0] = l01[h][1] = 0.f;
    }
    float o[2][8][4];
#pragma unroll
    for (int h = 0; h < 2; h++)
#pragma unroll
        for (int dt = 0; dt < 8; dt++)
#pragma unroll
            for (int i = 0; i < 4; i++) o[h][dt][i] = 0.f;

    for (int kb = 0; kb < NPOS / 64; kb++) {
        __syncthreads();
        const float* kg = g_kk + (size_t)(b * NPOS + kb * 64) * CB;
        const float* vg = g_v  + (size_t)(b * NPOS + kb * 64) * CB;
        for (int idx = tid; idx < 64 * 64; idx += 128) {
            int r = idx >> 6, c = idx & 63;
            float kv = kg[idx];
            __half hh = __float2half_rn(kv);
            Kh[r * SH + c] = hh;
            Kl[r * SH + c] = __float2half_rn(kv - __half2float(hh));
            Vt[c * SHV + r] = __float2half_rn(vg[idx]);
        }
        __syncthreads();

        // ---- S = Q K^T for both tiles; K frags loaded once ----
        float sc[2][8][4];
#pragma unroll
        for (int h = 0; h < 2; h++)
#pragma unroll
            for (int nt = 0; nt < 8; nt++)
#pragma unroll
                for (int i = 0; i < 4; i++) sc[h][nt][i] = 0.f;

#pragma unroll
        for (int ks = 0; ks < 4; ks++) {
            uint32_t a[2][4], e[2][4];
#pragma unroll
            for (int h = 0; h < 2; h++) {
                const __half* qp = Qh + (w * 32 + h * 16 + grp) * SH + ks * 16 + 2 * qd;
                const __half* lp = Ql + (w * 32 + h * 16 + grp) * SH + ks * 16 + 2 * qd;
                a[h][0] = ld_h2(qp);     a[h][1] = ld_h2(qp + 8 * SH);
                a[h][2] = ld_h2(qp + 8); a[h][3] = ld_h2(qp + 8 * SH + 8);
                e[h][0] = ld_h2(lp);     e[h][1] = ld_h2(lp + 8 * SH);
                e[h][2] = ld_h2(lp + 8); e[h][3] = ld_h2(lp + 8 * SH + 8);
            }
#pragma unroll
            for (int nt = 0; nt < 8; nt++) {
                const __half* kp  = Kh + (nt * 8 + grp) * SH + ks * 16 + 2 * qd;
                const __half* klp = Kl + (nt * 8 + grp) * SH + ks * 16 + 2 * qd;
                uint32_t b0 = ld_h2(kp),  b1 = ld_h2(kp + 8);
                uint32_t c0 = ld_h2(klp), c1 = ld_h2(klp + 8);
#pragma unroll
                for (int h = 0; h < 2; h++) {
                    MMA16816(sc[h][nt], a[h][0], a[h][1], a[h][2], a[h][3], b0, b1);
                    MMA16816(sc[h][nt], a[h][0], a[h][1], a[h][2], a[h][3], c0, c1);
                    MMA16816(sc[h][nt], e[h][0], e[h][1], e[h][2], e[h][3], b0, b1);
                }
            }
        }

        // ---- online softmax: 4 row-sets (tile h, row grp / grp+8) ----
#pragma unroll
        for (int h = 0; h < 2; h++) {
            float mx0 = -INFINITY, mx1 = -INFINITY;
#pragma unroll
            for (int nt = 0; nt < 8; nt++) {
                mx0 = fmaxf(mx0, fmaxf(sc[h][nt][0], sc[h][nt][1]));
                mx1 = fmaxf(mx1, fmaxf(sc[h][nt][2], sc[h][nt][3]));
            }
#pragma unroll
            for (int off = 1; off <= 2; off <<= 1) {
                mx0 = fmaxf(mx0, __shfl_xor_sync(0xffffffffu, mx0, off));
                mx1 = fmaxf(mx1, __shfl_xor_sync(0xffffffffu, mx1, off));
            }
            float mn0 = fmaxf(m01[h][0], mx0);
            float mn1 = fmaxf(m01[h][1], mx1);
            float s0 = __expf(m01[h][0] - mn0);
            float s1 = __expf(m01[h][1] - mn1);
            float rs0 = 0.f, rs1 = 0.f;
#pragma unroll
            for (int nt = 0; nt < 8; nt++) {
                sc[h][nt][0] = __expf(sc[h][nt][0] - mn0);
                sc[h][nt][1] = __expf(sc[h][nt][1] - mn0);
                sc[h][nt][2] = __expf(sc[h][nt][2] - mn1);
                sc[h][nt][3] = __expf(sc[h][nt][3] - mn1);
                rs0 += sc[h][nt][0] + sc[h][nt][1];
                rs1 += sc[h][nt][2] + sc[h][nt][3];
            }
#pragma unroll
            for (int off = 1; off <= 2; off <<= 1) {
                rs0 += __shfl_xor_sync(0xffffffffu, rs0, off);
                rs1 += __shfl_xor_sync(0xffffffffu, rs1, off);
            }
            l01[h][0] = l01[h][0] * s0 + rs0;  m01[h][0] = mn0;
            l01[h][1] = l01[h][1] * s1 + rs1;  m01[h][1] = mn1;
#pragma unroll
            for (int dt = 0; dt < 8; dt++) {
                o[h][dt][0] *= s0; o[h][dt][1] *= s0;
                o[h][dt][2] *= s1; o[h][dt][3] *= s1;
            }
        }

        // ---- O += P V ; V frags loaded once, used by both tiles ----
#pragma unroll
        for (int kc = 0; kc < 4; kc++) {
            uint32_t pa[2][4];
#pragma unroll
            for (int h = 0; h < 2; h++) {
                pa[h][0] = pack_h2(sc[h][2*kc][0],   sc[h][2*kc][1]);
                pa[h][1] = pack_h2(sc[h][2*kc][2],   sc[h][2*kc][3]);
                pa[h][2] = pack_h2(sc[h][2*kc+1][0], sc[h][2*kc+1][1]);
                pa[h][3] = pack_h2(sc[h][2*kc+1][2], sc[h][2*kc+1][3]);
            }
#pragma unroll
            for (int dt = 0; dt < 8; dt++) {
                const __half* vp = Vt + (dt * 8 + grp) * SHV + kc * 16 + 2 * qd;
                uint32_t b0 = ld_h2(vp), b1 = ld_h2(vp + 8);
#pragma unroll
                for (int h = 0; h < 2; h++)
                    MMA16816(o[h][dt], pa[h][0], pa[h][1], pa[h][2], pa[h][3], b0, b1);
            }
        }
    }

    float* yg = g_y + (size_t)(b * NPOS + n0) * CB;
#pragma unroll
    for (int h = 0; h < 2; h++) {
        float inv0 = 1.f / l01[h][0], inv1 = 1.f / l01[h][1];
        int r = w * 32 + h * 16 + grp;
#pragma unroll
        for (int dt = 0; dt < 8; dt++) {
            int d = dt * 8 + 2 * qd;
            *(float2*)&yg[r * CB + d] =
                make_float2(o[h][dt][0] * inv0, o[h][dt][1] * inv0);
            *(float2*)&yg[(r + 8) * CB + d] =
                make_float2(o[h][dt][2] * inv1, o[h][dt][3] * inv1);
        }
    }
}

// ---------------------------------------------------------------------------
// Kernel 3: out = w_last @ y + x  (FFMA2 inner loop)
// ---------------------------------------------------------------------------
__global__ void __launch_bounds__(256) out_kernel(
    const float* __restrict__ x, const float* __restrict__ wl,
    float* __restrict__ out)
{
    extern __shared__ float sm[];
    float* ys = sm;               // [64 n][65] : ys[n][k]
    float* ws = ys + 64 * 65;     // [64 k][132]: ws[k][c]
    const int b  = blockIdx.y;
    const int n0 = blockIdx.x * 64;
    const int tid = threadIdx.x;

    const float* yg = g_y + (size_t)(b * NPOS + n0) * CB;
    for (int idx = tid; idx < 64 * 64; idx += 256) {
        int n = idx >> 6, k = idx & 63;
        ys[n * 65 + k] = yg[idx];
    }
    for (int i = tid; i < CIN * CB; i += 256) {
        int c = i >> 6, k = i & 63;
        ws[k * 132 + c] = wl[i];
    }
    __syncthreads();

    const int n  = tid & 63;
    const int cb = (tid >> 6) * 32;
    unsigned long long acc2[16];
#pragma unroll
    for (int i = 0; i < 16; i++) acc2[i] = 0ull;

    for (int k = 0; k < CB; k++) {
        float yv = ys[n * 65 + k];
        unsigned long long yp = pk2(yv, yv);
        const double2* wr = (const double2*)(ws + k * 132 + cb);
#pragma unroll
        for (int q = 0; q < 8; q++) {
            double2 wv = wr[q];
            fma2(acc2[2*q],   __double_as_longlong(wv.x), yp);
            fma2(acc2[2*q+1], __double_as_longlong(wv.y), yp);
        }
    }
#pragma unroll
    for (int q = 0; q < 16; q++) {
        float2 t = upk2(acc2[q]);
        int o0 = (b * CIN + cb + 2 * q) * NPOS + n0 + n;
        out[o0]        = t.x + x[o0];
        out[o0 + NPOS] = t.y + x[o0 + NPOS];
    }
}

// ---------------------------------------------------------------------------
extern "C" void kernel_launch(void* const* d_in, const int* in_sizes, int n_in,
                              void* d_out, int out_size)
{
    const float* x  = (const float*)d_in[0];
    const float* wt = (const float*)d_in[1];
    const float* wp = (const float*)d_in[2];
    const float* wg = (const float*)d_in[3];
    const float* wl = (const float*)d_in[4];
    float* out = (float*)d_out;

    int smem1 = 3 * CIN * 65 * (int)sizeof(float);                             // 99,840 B
    int smem2 = (2 * 128 * SH + 2 * 64 * SH + 64 * SHV) * (int)sizeof(__half); // 64,256 B
    int smem3 = (64 * 65 + 64 * 132) * (int)sizeof(float);                     // 50,432 B
    cudaFuncSetAttribute(proj_kernel, cudaFuncAttributeMaxDynamicSharedMemorySize, smem1);
    cudaFuncSetAttribute(attn_kernel, cudaFuncAttributeMaxDynamicSharedMemorySize, smem2);
    cudaFuncSetAttribute(out_kernel,  cudaFuncAttributeMaxDynamicSharedMemorySize, smem3);

    dim3 grid1(NPOS / 64, NB);
    dim3 grid2(NPOS / 128, NB);
    proj_kernel<<<grid1, 256, smem1>>>(x, wt, wp, wg);
    attn_kernel<<<grid2, 128, smem2>>>();
    out_kernel<<<grid1, 256, smem3>>>(x, wl, out);
}

// round 6
// speedup vs baseline: 3.8722x; 1.2702x over previous
#include <cuda_runtime.h>
#include <cuda_fp16.h>
#include <math.h>
#include <stdint.h>

#define NB   8
#define CIN  128
#define CB   64
#define NPOS 4096
#define SH   72   // smem stride (halves) for all attn tiles: conflict-free frags

// fp16 operands, pre-converted by proj: [b][n][64] (hi/lo) ; vt: [b][d][n]
__device__ __align__(16) __half g_qh[NB * NPOS * CB];
__device__ __align__(16) __half g_ql[NB * NPOS * CB];
__device__ __align__(16) __half g_kh[NB * NPOS * CB];
__device__ __align__(16) __half g_kl[NB * NPOS * CB];
__device__ __align__(16) __half g_vt[NB * CB * NPOS];
__device__ __align__(16) float  g_y [NB * NPOS * CB];

// ---- packed fp32 helpers (used in out_kernel) ------------------------------
__device__ __forceinline__ void fma2(unsigned long long& d,
                                     unsigned long long a, unsigned long long b) {
    asm("fma.rn.f32x2 %0, %1, %2, %0;" : "+l"(d) : "l"(a), "l"(b));
}
__device__ __forceinline__ unsigned long long pk2(float lo, float hi) {
    unsigned long long r;
    asm("mov.b64 %0, {%1, %2};" : "=l"(r) : "f"(lo), "f"(hi));
    return r;
}
__device__ __forceinline__ float2 upk2(unsigned long long v) {
    float2 r;
    asm("mov.b64 {%0, %1}, %2;" : "=f"(r.x), "=f"(r.y) : "l"(v));
    return r;
}

// ---- cp.async helpers ------------------------------------------------------
__device__ __forceinline__ void cpasync16(uint32_t saddr, const void* g) {
    asm volatile("cp.async.ca.shared.global [%0], [%1], 16;"
                 :: "r"(saddr), "l"(g) : "memory");
}
#define CP_COMMIT() asm volatile("cp.async.commit_group;" ::: "memory")
#define CP_WAIT0()  asm volatile("cp.async.wait_group 0;" ::: "memory")

// ---------------------------------------------------------------------------
// Kernel 1: theta/phi/g = W @ x, smem-staged scalar FFMA (R2-proven form),
// epilogue converts to fp16 hi/lo (q,k) and fp16 transposed v.
// ---------------------------------------------------------------------------
__global__ void __launch_bounds__(256) proj_kernel(
    const float* __restrict__ x, const float* __restrict__ wt,
    const float* __restrict__ wp, const float* __restrict__ wg)
{
    extern __shared__ float sm[];
    float* xs = sm;               // [128][64]   xs[c][n]
    float* ws = sm + CIN * 64;    // 3 x [128][65], transposed: ws[c][k]
    const int b  = blockIdx.y;
    const int n0 = blockIdx.x * 64;
    const int tid = threadIdx.x;

    for (int i = tid; i < CIN * 64; i += 256) {
        int c = i >> 6, j = i & 63;
        xs[i] = x[(b * CIN + c) * NPOS + n0 + j];
    }
    for (int i = tid; i < CB * CIN; i += 256) {
        int k = i >> 7, c = i & 127;
        ws[c * 65 + k]                = wt[i];
        ws[CIN * 65 + c * 65 + k]     = wp[i];
        ws[2 * CIN * 65 + c * 65 + k] = wg[i];
    }
    __syncthreads();

    const int k  = tid & 63;
    const int nb = (tid >> 6) * 16;
    float at[16], ap[16], ag[16];
#pragma unroll
    for (int i = 0; i < 16; i++) { at[i] = 0.f; ap[i] = 0.f; ag[i] = 0.f; }

    for (int c = 0; c < CIN; c++) {
        float w0 = ws[c * 65 + k];
        float w1 = ws[CIN * 65 + c * 65 + k];
        float w2 = ws[2 * CIN * 65 + c * 65 + k];
        const float4* xr = (const float4*)(xs + c * 64 + nb);
#pragma unroll
        for (int q = 0; q < 4; q++) {
            float4 xv = xr[q];
            at[4*q+0] += w0 * xv.x; at[4*q+1] += w0 * xv.y;
            at[4*q+2] += w0 * xv.z; at[4*q+3] += w0 * xv.w;
            ap[4*q+0] += w1 * xv.x; ap[4*q+1] += w1 * xv.y;
            ap[4*q+2] += w1 * xv.z; ap[4*q+3] += w1 * xv.w;
            ag[4*q+0] += w2 * xv.x; ag[4*q+1] += w2 * xv.y;
            ag[4*q+2] += w2 * xv.z; ag[4*q+3] += w2 * xv.w;
        }
    }
#pragma unroll
    for (int i = 0; i < 16; i++) {
        int n = n0 + nb + i;
        int o = (b * NPOS + n) * CB + k;
        float tq = at[i];
        __half th = __float2half_rn(tq);
        g_qh[o] = th;
        g_ql[o] = __float2half_rn(tq - __half2float(th));
        float tk = ap[i];
        __half kh = __float2half_rn(tk);
        g_kh[o] = kh;
        g_kl[o] = __float2half_rn(tk - __half2float(kh));
        g_vt[((size_t)b * CB + k) * NPOS + n] = __float2half_rn(ag[i]);
    }
}

// ---------------------------------------------------------------------------
// Kernel 2: flash attention, mma.sync m16n8k16 fp16/fp32, hi/lo logit split.
// CTA = 128 q rows, 128 threads (4 warps x two 16-row tiles).
// cp.async double-buffered K/V staging from pre-converted fp16 operands.
// ---------------------------------------------------------------------------
#define MMA16816(C, A0, A1, A2, A3, B0, B1)                                   \
    asm volatile("mma.sync.aligned.m16n8k16.row.col.f32.f16.f16.f32 "         \
                 "{%0,%1,%2,%3}, {%4,%5,%6,%7}, {%8,%9}, {%0,%1,%2,%3};"      \
                 : "+f"(C[0]), "+f"(C[1]), "+f"(C[2]), "+f"(C[3])             \
                 : "r"(A0), "r"(A1), "r"(A2), "r"(A3), "r"(B0), "r"(B1))

__device__ __forceinline__ uint32_t ld_h2(const __half* p) {
    return *(const uint32_t*)p;
}
__device__ __forceinline__ uint32_t pack_h2(float a, float b) {
    __half2 h = __floats2half2_rn(a, b);
    return *(uint32_t*)&h;
}

// smem layout (halves): Qh[128*SH] | Ql[128*SH] | 2 x { Kh[64*SH] | Kl[64*SH] | Vt[64*SH] }
#define OQ_H  0
#define OQ_L  (128 * SH)
#define OKV   (2 * 128 * SH)
#define KVSZ  (3 * 64 * SH)
#define OK_L  (64 * SH)
#define OV_T  (2 * 64 * SH)

__global__ void __launch_bounds__(128, 2) attn_kernel()
{
    extern __shared__ __half hsm[];
    const int b   = blockIdx.y;
    const int n0  = blockIdx.x * 128;
    const int tid = threadIdx.x;
    const int w    = tid >> 5;
    const int lane = tid & 31;
    const int grp  = lane >> 4 ? 0 : 0;  // placeholder avoid warning
    const int g8   = (lane >> 2);        // fragment row group 0..7
    const int qd   = lane & 3;

    const uint32_t sbase = (uint32_t)__cvta_generic_to_shared(hsm);

    const __half* khg_b = g_kh + (size_t)b * NPOS * CB;
    const __half* klg_b = g_kl + (size_t)b * NPOS * CB;
    const __half* vtg_b = g_vt + (size_t)b * CB * NPOS;

    // chunk mapping for staging: 512 chunks (64 rows x 8 cols) per array
    const int r0 = tid >> 3;          // rows tid/8 + {0,16,32,48}
    const int c0 = tid & 7;

    // ---- prologue: issue kb=0 into buf 0 ----
    {
        const __half* khg = khg_b;    // kb=0
        const __half* klg = klg_b;
        uint32_t skv = sbase + OKV * 2;
#pragma unroll
        for (int i = 0; i < 4; i++) {
            int r = r0 + i * 16;
            cpasync16(skv + (r * SH + c0 * 8) * 2,            khg + r * CB + c0 * 8);
            cpasync16(skv + (OK_L + r * SH + c0 * 8) * 2,     klg + r * CB + c0 * 8);
            cpasync16(skv + (OV_T + r * SH + c0 * 8) * 2,     vtg_b + (size_t)r * NPOS + c0 * 8);
        }
    }
    CP_COMMIT();

    // ---- stage Q (128 rows, hi+lo) from pre-converted gmem ----
    {
        const uint4* qh4 = (const uint4*)(g_qh + (size_t)(b * NPOS + n0) * CB);
        const uint4* ql4 = (const uint4*)(g_ql + (size_t)(b * NPOS + n0) * CB);
#pragma unroll
        for (int i = 0; i < 8; i++) {
            int ch = tid + i * 128;          // 0..1023
            int r = ch >> 3, cc = ch & 7;
            *(uint4*)(hsm + OQ_H + r * SH + cc * 8) = qh4[r * 8 + cc];
            *(uint4*)(hsm + OQ_L + r * SH + cc * 8) = ql4[r * 8 + cc];
        }
    }

    float m01[2][2], l01[2][2];
#pragma unroll
    for (int h = 0; h < 2; h++) {
        m01[h][0] = m01[h][1] = -INFINITY;
        l01[h][0] = l01[h][1] = 0.f;
    }
    float o[2][8][4];
#pragma unroll
    for (int h = 0; h < 2; h++)
#pragma unroll
        for (int dt = 0; dt < 8; dt++)
#pragma unroll
            for (int i = 0; i < 4; i++) o[h][dt][i] = 0.f;

    for (int kb = 0; kb < NPOS / 64; kb++) {
        const int p = kb & 1;
        CP_WAIT0();
        __syncthreads();

        // issue next block into the other buffer (overlaps with compute below)
        if (kb + 1 < NPOS / 64) {
            const __half* khg = khg_b + (size_t)(kb + 1) * 64 * CB;
            const __half* klg = klg_b + (size_t)(kb + 1) * 64 * CB;
            const __half* vtg = vtg_b + (size_t)(kb + 1) * 64;
            uint32_t skv = sbase + (OKV + (p ^ 1) * KVSZ) * 2;
#pragma unroll
            for (int i = 0; i < 4; i++) {
                int r = r0 + i * 16;
                cpasync16(skv + (r * SH + c0 * 8) * 2,        khg + r * CB + c0 * 8);
                cpasync16(skv + (OK_L + r * SH + c0 * 8) * 2, klg + r * CB + c0 * 8);
                cpasync16(skv + (OV_T + r * SH + c0 * 8) * 2, vtg + (size_t)r * NPOS + c0 * 8);
            }
        }
        CP_COMMIT();

        const __half* Kh = hsm + OKV + p * KVSZ;
        const __half* Kl = Kh + OK_L;
        const __half* Vt = Kh + OV_T;

        // ---- S = Q K^T for both tiles; K frags loaded once ----
        float sc[2][8][4];
#pragma unroll
        for (int h = 0; h < 2; h++)
#pragma unroll
            for (int nt = 0; nt < 8; nt++)
#pragma unroll
                for (int i = 0; i < 4; i++) sc[h][nt][i] = 0.f;

#pragma unroll
        for (int ks = 0; ks < 4; ks++) {
            uint32_t a[2][4], e[2][4];
#pragma unroll
            for (int h = 0; h < 2; h++) {
                const __half* qp = hsm + OQ_H + (w * 32 + h * 16 + g8) * SH + ks * 16 + 2 * qd;
                const __half* lp = hsm + OQ_L + (w * 32 + h * 16 + g8) * SH + ks * 16 + 2 * qd;
                a[h][0] = ld_h2(qp);     a[h][1] = ld_h2(qp + 8 * SH);
                a[h][2] = ld_h2(qp + 8); a[h][3] = ld_h2(qp + 8 * SH + 8);
                e[h][0] = ld_h2(lp);     e[h][1] = ld_h2(lp + 8 * SH);
                e[h][2] = ld_h2(lp + 8); e[h][3] = ld_h2(lp + 8 * SH + 8);
            }
#pragma unroll
            for (int nt = 0; nt < 8; nt++) {
                const __half* kp  = Kh + (nt * 8 + g8) * SH + ks * 16 + 2 * qd;
                const __half* klp = Kl + (nt * 8 + g8) * SH + ks * 16 + 2 * qd;
                uint32_t b0 = ld_h2(kp),  b1 = ld_h2(kp + 8);
                uint32_t c0f = ld_h2(klp), c1f = ld_h2(klp + 8);
#pragma unroll
                for (int h = 0; h < 2; h++) {
                    MMA16816(sc[h][nt], a[h][0], a[h][1], a[h][2], a[h][3], b0, b1);
                    MMA16816(sc[h][nt], a[h][0], a[h][1], a[h][2], a[h][3], c0f, c1f);
                    MMA16816(sc[h][nt], e[h][0], e[h][1], e[h][2], e[h][3], b0, b1);
                }
            }
        }

        // ---- online softmax: 4 row-sets (tile h, row g8 / g8+8) ----
#pragma unroll
        for (int h = 0; h < 2; h++) {
            float mx0 = -INFINITY, mx1 = -INFINITY;
#pragma unroll
            for (int nt = 0; nt < 8; nt++) {
                mx0 = fmaxf(mx0, fmaxf(sc[h][nt][0], sc[h][nt][1]));
                mx1 = fmaxf(mx1, fmaxf(sc[h][nt][2], sc[h][nt][3]));
            }
#pragma unroll
            for (int off = 1; off <= 2; off <<= 1) {
                mx0 = fmaxf(mx0, __shfl_xor_sync(0xffffffffu, mx0, off));
                mx1 = fmaxf(mx1, __shfl_xor_sync(0xffffffffu, mx1, off));
            }
            float mn0 = fmaxf(m01[h][0], mx0);
            float mn1 = fmaxf(m01[h][1], mx1);
            float s0 = __expf(m01[h][0] - mn0);
            float s1 = __expf(m01[h][1] - mn1);
            float rs0 = 0.f, rs1 = 0.f;
#pragma unroll
            for (int nt = 0; nt < 8; nt++) {
                sc[h][nt][0] = __expf(sc[h][nt][0] - mn0);
                sc[h][nt][1] = __expf(sc[h][nt][1] - mn0);
                sc[h][nt][2] = __expf(sc[h][nt][2] - mn1);
                sc[h][nt][3] = __expf(sc[h][nt][3] - mn1);
                rs0 += sc[h][nt][0] + sc[h][nt][1];
                rs1 += sc[h][nt][2] + sc[h][nt][3];
            }
#pragma unroll
            for (int off = 1; off <= 2; off <<= 1) {
                rs0 += __shfl_xor_sync(0xffffffffu, rs0, off);
                rs1 += __shfl_xor_sync(0xffffffffu, rs1, off);
            }
            l01[h][0] = l01[h][0] * s0 + rs0;  m01[h][0] = mn0;
            l01[h][1] = l01[h][1] * s1 + rs1;  m01[h][1] = mn1;
#pragma unroll
            for (int dt = 0; dt < 8; dt++) {
                o[h][dt][0] *= s0; o[h][dt][1] *= s0;
                o[h][dt][2] *= s1; o[h][dt][3] *= s1;
            }
        }

        // ---- O += P V ; V frags loaded once, used by both tiles ----
#pragma unroll
        for (int kc = 0; kc < 4; kc++) {
            uint32_t pa[2][4];
#pragma unroll
            for (int h = 0; h < 2; h++) {
                pa[h][0] = pack_h2(sc[h][2*kc][0],   sc[h][2*kc][1]);
                pa[h][1] = pack_h2(sc[h][2*kc][2],   sc[h][2*kc][3]);
                pa[h][2] = pack_h2(sc[h][2*kc+1][0], sc[h][2*kc+1][1]);
                pa[h][3] = pack_h2(sc[h][2*kc+1][2], sc[h][2*kc+1][3]);
            }
#pragma unroll
            for (int dt = 0; dt < 8; dt++) {
                const __half* vp = Vt + (dt * 8 + g8) * SH + kc * 16 + 2 * qd;
                uint32_t b0 = ld_h2(vp), b1 = ld_h2(vp + 8);
#pragma unroll
                for (int h = 0; h < 2; h++)
                    MMA16816(o[h][dt], pa[h][0], pa[h][1], pa[h][2], pa[h][3], b0, b1);
            }
        }
    }

    float* yg = g_y + (size_t)(b * NPOS + n0) * CB;
#pragma unroll
    for (int h = 0; h < 2; h++) {
        float inv0 = 1.f / l01[h][0], inv1 = 1.f / l01[h][1];
        int r = w * 32 + h * 16 + g8;
#pragma unroll
        for (int dt = 0; dt < 8; dt++) {
            int d = dt * 8 + 2 * qd;
            *(float2*)&yg[r * CB + d] =
                make_float2(o[h][dt][0] * inv0, o[h][dt][1] * inv0);
            *(float2*)&yg[(r + 8) * CB + d] =
                make_float2(o[h][dt][2] * inv1, o[h][dt][3] * inv1);
        }
    }
    (void)grp;
}

// ---------------------------------------------------------------------------
// Kernel 3: out = w_last @ y + x  (FFMA2 inner loop)
// ---------------------------------------------------------------------------
__global__ void __launch_bounds__(256) out_kernel(
    const float* __restrict__ x, const float* __restrict__ wl,
    float* __restrict__ out)
{
    extern __shared__ float sm[];
    float* ys = sm;               // [64 n][65] : ys[n][k]
    float* ws = ys + 64 * 65;     // [64 k][132]: ws[k][c]
    const int b  = blockIdx.y;
    const int n0 = blockIdx.x * 64;
    const int tid = threadIdx.x;

    const float* yg = g_y + (size_t)(b * NPOS + n0) * CB;
    for (int idx = tid; idx < 64 * 64; idx += 256) {
        int n = idx >> 6, k = idx & 63;
        ys[n * 65 + k] = yg[idx];
    }
    for (int i = tid; i < CIN * CB; i += 256) {
        int c = i >> 6, k = i & 63;
        ws[k * 132 + c] = wl[i];
    }
    __syncthreads();

    const int n  = tid & 63;
    const int cb = (tid >> 6) * 32;
    unsigned long long acc2[16];
#pragma unroll
    for (int i = 0; i < 16; i++) acc2[i] = 0ull;

    for (int k = 0; k < CB; k++) {
        float yv = ys[n * 65 + k];
        unsigned long long yp = pk2(yv, yv);
        const double2* wr = (const double2*)(ws + k * 132 + cb);
#pragma unroll
        for (int q = 0; q < 8; q++) {
            double2 wv = wr[q];
            fma2(acc2[2*q],   __double_as_longlong(wv.x), yp);
            fma2(acc2[2*q+1], __double_as_longlong(wv.y), yp);
        }
    }
#pragma unroll
    for (int q = 0; q < 16; q++) {
        float2 t = upk2(acc2[q]);
        int o0 = (b * CIN + cb + 2 * q) * NPOS + n0 + n;
        out[o0]        = t.x + x[o0];
        out[o0 + NPOS] = t.y + x[o0 + NPOS];
    }
}

// ---------------------------------------------------------------------------
extern "C" void kernel_launch(void* const* d_in, const int* in_sizes, int n_in,
                              void* d_out, int out_size)
{
    const float* x  = (const float*)d_in[0];
    const float* wt = (const float*)d_in[1];
    const float* wp = (const float*)d_in[2];
    const float* wg = (const float*)d_in[3];
    const float* wl = (const float*)d_in[4];
    float* out = (float*)d_out;

    int smem1 = (CIN * 64 + 3 * CIN * 65) * (int)sizeof(float);        // 132,608 B
    int smem2 = (2 * 128 * SH + 2 * KVSZ) * (int)sizeof(__half);       //  92,160 B
    int smem3 = (64 * 65 + 64 * 132) * (int)sizeof(float);             //  50,432 B
    cudaFuncSetAttribute(proj_kernel, cudaFuncAttributeMaxDynamicSharedMemorySize, smem1);
    cudaFuncSetAttribute(attn_kernel, cudaFuncAttributeMaxDynamicSharedMemorySize, smem2);
    cudaFuncSetAttribute(out_kernel,  cudaFuncAttributeMaxDynamicSharedMemorySize, smem3);

    dim3 grid1(NPOS / 64, NB);
    dim3 grid2(NPOS / 128, NB);
    proj_kernel<<<grid1, 256, smem1>>>(x, wt, wp, wg);
    attn_kernel<<<grid2, 128, smem2>>>();
    out_kernel<<<grid1, 256, smem3>>>(x, wl, out);
}

// round 7
// speedup vs baseline: 4.3131x; 1.1139x over previous
#include <cuda_runtime.h>
#include <cuda_fp16.h>
#include <math.h>
#include <stdint.h>

#define NB   8
#define CIN  128
#define CB   64
#define NPOS 4096
#define SH   72   // smem stride (halves) for all attn tiles: conflict-free frags/LDSM

// fp16 operands, pre-converted by proj: [b][n][64] (hi/lo) ; vt: [b][d][n]
__device__ __align__(16) __half g_qh[NB * NPOS * CB];
__device__ __align__(16) __half g_ql[NB * NPOS * CB];
__device__ __align__(16) __half g_kh[NB * NPOS * CB];
__device__ __align__(16) __half g_kl[NB * NPOS * CB];
__device__ __align__(16) __half g_vt[NB * CB * NPOS];
__device__ __align__(16) float  g_y [NB * NPOS * CB];

// ---- packed fp32 helpers (out_kernel) --------------------------------------
__device__ __forceinline__ void fma2(unsigned long long& d,
                                     unsigned long long a, unsigned long long b) {
    asm("fma.rn.f32x2 %0, %1, %2, %0;" : "+l"(d) : "l"(a), "l"(b));
}
__device__ __forceinline__ unsigned long long pk2(float lo, float hi) {
    unsigned long long r;
    asm("mov.b64 %0, {%1, %2};" : "=l"(r) : "f"(lo), "f"(hi));
    return r;
}
__device__ __forceinline__ float2 upk2(unsigned long long v) {
    float2 r;
    asm("mov.b64 {%0, %1}, %2;" : "=f"(r.x), "=f"(r.y) : "l"(v));
    return r;
}

// ---- cp.async helpers ------------------------------------------------------
__device__ __forceinline__ void cpasync16(uint32_t saddr, const void* g) {
    asm volatile("cp.async.ca.shared.global [%0], [%1], 16;"
                 :: "r"(saddr), "l"(g) : "memory");
}
#define CP_COMMIT() asm volatile("cp.async.commit_group;" ::: "memory")
#define CP_WAIT0()  asm volatile("cp.async.wait_group 0;" ::: "memory")

// ---------------------------------------------------------------------------
// Kernel 1: theta/phi/g = W @ x (smem-staged scalar FFMA), epilogue emits
// fp16 hi/lo q,k (coalesced) and fp16 v transposed via smem (coalesced 16B STG).
// ---------------------------------------------------------------------------
__global__ void __launch_bounds__(256) proj_kernel(
    const float* __restrict__ x, const float* __restrict__ wt,
    const float* __restrict__ wp, const float* __restrict__ wg)
{
    extern __shared__ float sm[];
    float* xs = sm;               // [128][64]   xs[c][n]
    float* ws = sm + CIN * 64;    // 3 x [128][65], transposed: ws[c][k]
    const int b  = blockIdx.y;
    const int n0 = blockIdx.x * 64;
    const int tid = threadIdx.x;

    for (int i = tid; i < CIN * 64; i += 256) {
        int c = i >> 6, j = i & 63;
        xs[i] = x[(b * CIN + c) * NPOS + n0 + j];
    }
    for (int i = tid; i < CB * CIN; i += 256) {
        int k = i >> 7, c = i & 127;
        ws[c * 65 + k]                = wt[i];
        ws[CIN * 65 + c * 65 + k]     = wp[i];
        ws[2 * CIN * 65 + c * 65 + k] = wg[i];
    }
    __syncthreads();

    const int k  = tid & 63;
    const int nb = (tid >> 6) * 16;
    float at[16], ap[16], ag[16];
#pragma unroll
    for (int i = 0; i < 16; i++) { at[i] = 0.f; ap[i] = 0.f; ag[i] = 0.f; }

    for (int c = 0; c < CIN; c++) {
        float w0 = ws[c * 65 + k];
        float w1 = ws[CIN * 65 + c * 65 + k];
        float w2 = ws[2 * CIN * 65 + c * 65 + k];
        const float4* xr = (const float4*)(xs + c * 64 + nb);
#pragma unroll
        for (int q = 0; q < 4; q++) {
            float4 xv = xr[q];
            at[4*q+0] += w0 * xv.x; at[4*q+1] += w0 * xv.y;
            at[4*q+2] += w0 * xv.z; at[4*q+3] += w0 * xv.w;
            ap[4*q+0] += w1 * xv.x; ap[4*q+1] += w1 * xv.y;
            ap[4*q+2] += w1 * xv.z; ap[4*q+3] += w1 * xv.w;
            ag[4*q+0] += w2 * xv.x; ag[4*q+1] += w2 * xv.y;
            ag[4*q+2] += w2 * xv.z; ag[4*q+3] += w2 * xv.w;
        }
    }

    // q/k hi-lo: coalesced 2B stores (lanes span contiguous k)
#pragma unroll
    for (int i = 0; i < 16; i++) {
        int n = n0 + nb + i;
        int o = (b * NPOS + n) * CB + k;
        float tq = at[i];
        __half th = __float2half_rn(tq);
        g_qh[o] = th;
        g_ql[o] = __float2half_rn(tq - __half2float(th));
        float tk = ap[i];
        __half kh = __float2half_rn(tk);
        g_kh[o] = kh;
        g_kl[o] = __float2half_rn(tk - __half2float(kh));
    }

    // v: transpose through smem, then coalesced 16B row writes
    __syncthreads();                       // done with xs/ws
    __half* vs = (__half*)sm;              // [64 k][72]  (144B rows, 16B aligned)
#pragma unroll
    for (int i = 0; i < 16; i++)
        vs[k * SH + nb + i] = __float2half_rn(ag[i]);
    __syncthreads();
#pragma unroll
    for (int it = 0; it < 2; it++) {
        int ch = tid + it * 256;           // 512 chunks: 64 rows x 8 x 16B
        int kk = ch >> 3, cc = ch & 7;
        *(uint4*)(g_vt + ((size_t)b * CB + kk) * NPOS + n0 + cc * 8) =
            *(const uint4*)(vs + kk * SH + cc * 8);
    }
}

// ---------------------------------------------------------------------------
// Kernel 2: flash attention, mma.sync m16n8k16 fp16/fp32, hi/lo logit split.
// CTA = 128 q rows, 128 threads. ldmatrix.x4 fragment loads; cp.async
// double-buffered K/V staging from pre-converted fp16 operands.
// ---------------------------------------------------------------------------
#define MMA16816(C, A0, A1, A2, A3, B0, B1)                                   \
    asm volatile("mma.sync.aligned.m16n8k16.row.col.f32.f16.f16.f32 "         \
                 "{%0,%1,%2,%3}, {%4,%5,%6,%7}, {%8,%9}, {%0,%1,%2,%3};"      \
                 : "+f"(C[0]), "+f"(C[1]), "+f"(C[2]), "+f"(C[3])             \
                 : "r"(A0), "r"(A1), "r"(A2), "r"(A3), "r"(B0), "r"(B1))

#define LDSM4(R0, R1, R2, R3, ADDR)                                           \
    asm volatile("ldmatrix.sync.aligned.m8n8.x4.shared.b16 {%0,%1,%2,%3}, [%4];" \
                 : "=r"(R0), "=r"(R1), "=r"(R2), "=r"(R3) : "r"(ADDR))

__device__ __forceinline__ uint32_t pack_h2(float a, float b) {
    __half2 h = __floats2half2_rn(a, b);
    return *(uint32_t*)&h;
}

// smem layout (halves): Qh[128*SH] | Ql[128*SH] | 2 x { Kh[64*SH] | Kl[64*SH] | Vt[64*SH] }
#define OQ_H  0
#define OQ_L  (128 * SH)
#define OKV   (2 * 128 * SH)
#define KVSZ  (3 * 64 * SH)
#define OK_L  (64 * SH)
#define OV_T  (2 * 64 * SH)

__global__ void __launch_bounds__(128, 2) attn_kernel()
{
    extern __shared__ __half hsm[];
    const int b   = blockIdx.y;
    const int n0  = blockIdx.x * 128;
    const int tid = threadIdx.x;
    const int w    = tid >> 5;
    const int lane = tid & 31;
    const int g8   = lane >> 2;
    const int qd   = lane & 3;

    const uint32_t sbase = (uint32_t)__cvta_generic_to_shared(hsm);
    // ldmatrix per-lane byte offsets
    // A-pattern (Q): lanes 0-15 rows +0..15 col+0 ; lanes 16-31 rows +0..15 col+8
    const uint32_t qoff = (uint32_t)(((lane & 15) * SH + ((lane & 16) >> 1)) * 2);
    // B-pattern (K/V, 2 tiles): lanes 0-7 rows+0..7 col+0, 8-15 rows+0..7 col+8,
    //                           16-23 rows+8..15 col+0, 24-31 rows+8..15 col+8
    const uint32_t koff = (uint32_t)((((lane & 7) + ((lane & 16) >> 1)) * SH + (lane & 8)) * 2);

    const __half* khg_b = g_kh + (size_t)b * NPOS * CB;
    const __half* klg_b = g_kl + (size_t)b * NPOS * CB;
    const __half* vtg_b = g_vt + (size_t)b * CB * NPOS;

    const int r0 = tid >> 3;          // staging rows tid/8 + {0,16,32,48}
    const int c0 = tid & 7;

    // ---- prologue: issue kb=0 into buf 0 ----
    {
        uint32_t skv = sbase + OKV * 2;
#pragma unroll
        for (int i = 0; i < 4; i++) {
            int r = r0 + i * 16;
            cpasync16(skv + (r * SH + c0 * 8) * 2,        khg_b + r * CB + c0 * 8);
            cpasync16(skv + (OK_L + r * SH + c0 * 8) * 2, klg_b + r * CB + c0 * 8);
            cpasync16(skv + (OV_T + r * SH + c0 * 8) * 2, vtg_b + (size_t)r * NPOS + c0 * 8);
        }
    }
    CP_COMMIT();

    // ---- stage Q (128 rows, hi+lo) ----
    {
        const uint4* qh4 = (const uint4*)(g_qh + (size_t)(b * NPOS + n0) * CB);
        const uint4* ql4 = (const uint4*)(g_ql + (size_t)(b * NPOS + n0) * CB);
#pragma unroll
        for (int i = 0; i < 8; i++) {
            int ch = tid + i * 128;
            int r = ch >> 3, cc = ch & 7;
            *(uint4*)(hsm + OQ_H + r * SH + cc * 8) = qh4[r * 8 + cc];
            *(uint4*)(hsm + OQ_L + r * SH + cc * 8) = ql4[r * 8 + cc];
        }
    }

    float m01[2][2], l01[2][2];
#pragma unroll
    for (int h = 0; h < 2; h++) {
        m01[h][0] = m01[h][1] = -INFINITY;
        l01[h][0] = l01[h][1] = 0.f;
    }
    float o[2][8][4];
#pragma unroll
    for (int h = 0; h < 2; h++)
#pragma unroll
        for (int dt = 0; dt < 8; dt++)
#pragma unroll
            for (int i = 0; i < 4; i++) o[h][dt][i] = 0.f;

    for (int kb = 0; kb < NPOS / 64; kb++) {
        const int p = kb & 1;
        CP_WAIT0();
        __syncthreads();

        if (kb + 1 < NPOS / 64) {
            const __half* khg = khg_b + (size_t)(kb + 1) * 64 * CB;
            const __half* klg = klg_b + (size_t)(kb + 1) * 64 * CB;
            const __half* vtg = vtg_b + (size_t)(kb + 1) * 64;
            uint32_t skv = sbase + (OKV + (p ^ 1) * KVSZ) * 2;
#pragma unroll
            for (int i = 0; i < 4; i++) {
                int r = r0 + i * 16;
                cpasync16(skv + (r * SH + c0 * 8) * 2,        khg + r * CB + c0 * 8);
                cpasync16(skv + (OK_L + r * SH + c0 * 8) * 2, klg + r * CB + c0 * 8);
                cpasync16(skv + (OV_T + r * SH + c0 * 8) * 2, vtg + (size_t)r * NPOS + c0 * 8);
            }
        }
        CP_COMMIT();

        const uint32_t sKh = sbase + (OKV + p * KVSZ) * 2;
        const uint32_t sKl = sKh + OK_L * 2;
        const uint32_t sVt = sKh + OV_T * 2;

        // ---- S = Q K^T (both tiles); LDSM fragment loads ----
        float sc[2][8][4];
#pragma unroll
        for (int h = 0; h < 2; h++)
#pragma unroll
            for (int nt = 0; nt < 8; nt++)
#pragma unroll
                for (int i = 0; i < 4; i++) sc[h][nt][i] = 0.f;

#pragma unroll
        for (int ks = 0; ks < 4; ks++) {
            uint32_t a[2][4], e[2][4];
#pragma unroll
            for (int h = 0; h < 2; h++) {
                uint32_t qa = sbase + (OQ_H + (w * 32 + h * 16) * SH + ks * 16) * 2 + qoff;
                uint32_t la = sbase + (OQ_L + (w * 32 + h * 16) * SH + ks * 16) * 2 + qoff;
                LDSM4(a[h][0], a[h][1], a[h][2], a[h][3], qa);
                LDSM4(e[h][0], e[h][1], e[h][2], e[h][3], la);
            }
#pragma unroll
            for (int ntp = 0; ntp < 4; ntp++) {
                uint32_t kh0, kh1, kh2, kh3, kl0, kl1, kl2, kl3;
                uint32_t ka = sKh + (ntp * 16 * SH + ks * 16) * 2 + koff;
                uint32_t lb = sKl + (ntp * 16 * SH + ks * 16) * 2 + koff;
                LDSM4(kh0, kh1, kh2, kh3, ka);
                LDSM4(kl0, kl1, kl2, kl3, lb);
#pragma unroll
                for (int h = 0; h < 2; h++) {
                    MMA16816(sc[h][2*ntp],   a[h][0], a[h][1], a[h][2], a[h][3], kh0, kh1);
                    MMA16816(sc[h][2*ntp],   a[h][0], a[h][1], a[h][2], a[h][3], kl0, kl1);
                    MMA16816(sc[h][2*ntp],   e[h][0], e[h][1], e[h][2], e[h][3], kh0, kh1);
                    MMA16816(sc[h][2*ntp+1], a[h][0], a[h][1], a[h][2], a[h][3], kh2, kh3);
                    MMA16816(sc[h][2*ntp+1], a[h][0], a[h][1], a[h][2], a[h][3], kl2, kl3);
                    MMA16816(sc[h][2*ntp+1], e[h][0], e[h][1], e[h][2], e[h][3], kh2, kh3);
                }
            }
        }

        // ---- online softmax: 4 row-sets (tile h, row g8 / g8+8) ----
#pragma unroll
        for (int h = 0; h < 2; h++) {
            float mx0 = -INFINITY, mx1 = -INFINITY;
#pragma unroll
            for (int nt = 0; nt < 8; nt++) {
                mx0 = fmaxf(mx0, fmaxf(sc[h][nt][0], sc[h][nt][1]));
                mx1 = fmaxf(mx1, fmaxf(sc[h][nt][2], sc[h][nt][3]));
            }
#pragma unroll
            for (int off = 1; off <= 2; off <<= 1) {
                mx0 = fmaxf(mx0, __shfl_xor_sync(0xffffffffu, mx0, off));
                mx1 = fmaxf(mx1, __shfl_xor_sync(0xffffffffu, mx1, off));
            }
            float mn0 = fmaxf(m01[h][0], mx0);
            float mn1 = fmaxf(m01[h][1], mx1);
            float s0 = __expf(m01[h][0] - mn0);
            float s1 = __expf(m01[h][1] - mn1);
            float rs0 = 0.f, rs1 = 0.f;
#pragma unroll
            for (int nt = 0; nt < 8; nt++) {
                sc[h][nt][0] = __expf(sc[h][nt][0] - mn0);
                sc[h][nt][1] = __expf(sc[h][nt][1] - mn0);
                sc[h][nt][2] = __expf(sc[h][nt][2] - mn1);
                sc[h][nt][3] = __expf(sc[h][nt][3] - mn1);
                rs0 += sc[h][nt][0] + sc[h][nt][1];
                rs1 += sc[h][nt][2] + sc[h][nt][3];
            }
#pragma unroll
            for (int off = 1; off <= 2; off <<= 1) {
                rs0 += __shfl_xor_sync(0xffffffffu, rs0, off);
                rs1 += __shfl_xor_sync(0xffffffffu, rs1, off);
            }
            l01[h][0] = l01[h][0] * s0 + rs0;  m01[h][0] = mn0;
            l01[h][1] = l01[h][1] * s1 + rs1;  m01[h][1] = mn1;
#pragma unroll
            for (int dt = 0; dt < 8; dt++) {
                o[h][dt][0] *= s0; o[h][dt][1] *= s0;
                o[h][dt][2] *= s1; o[h][dt][3] *= s1;
            }
        }

        // ---- O += P V ; LDSM V frags, shared across both tiles ----
#pragma unroll
        for (int kc = 0; kc < 4; kc++) {
            uint32_t pa[2][4];
#pragma unroll
            for (int h = 0; h < 2; h++) {
                pa[h][0] = pack_h2(sc[h][2*kc][0],   sc[h][2*kc][1]);
                pa[h][1] = pack_h2(sc[h][2*kc][2],   sc[h][2*kc][3]);
                pa[h][2] = pack_h2(sc[h][2*kc+1][0], sc[h][2*kc+1][1]);
                pa[h][3] = pack_h2(sc[h][2*kc+1][2], sc[h][2*kc+1][3]);
            }
#pragma unroll
            for (int dtp = 0; dtp < 4; dtp++) {
                uint32_t v0, v1, v2, v3;
                uint32_t va = sVt + (dtp * 16 * SH + kc * 16) * 2 + koff;
                LDSM4(v0, v1, v2, v3, va);
#pragma unroll
                for (int h = 0; h < 2; h++) {
                    MMA16816(o[h][2*dtp],   pa[h][0], pa[h][1], pa[h][2], pa[h][3], v0, v1);
                    MMA16816(o[h][2*dtp+1], pa[h][0], pa[h][1], pa[h][2], pa[h][3], v2, v3);
                }
            }
        }
    }

    float* yg = g_y + (size_t)(b * NPOS + n0) * CB;
#pragma unroll
    for (int h = 0; h < 2; h++) {
        float inv0 = 1.f / l01[h][0], inv1 = 1.f / l01[h][1];
        int r = w * 32 + h * 16 + g8;
#pragma unroll
        for (int dt = 0; dt < 8; dt++) {
            int d = dt * 8 + 2 * qd;
            *(float2*)&yg[r * CB + d] =
                make_float2(o[h][dt][0] * inv0, o[h][dt][1] * inv0);
            *(float2*)&yg[(r + 8) * CB + d] =
                make_float2(o[h][dt][2] * inv1, o[h][dt][3] * inv1);
        }
    }
}

// ---------------------------------------------------------------------------
// Kernel 3: out = w_last @ y + x  (FFMA2 inner loop)
// ---------------------------------------------------------------------------
__global__ void __launch_bounds__(256) out_kernel(
    const float* __restrict__ x, const float* __restrict__ wl,
    float* __restrict__ out)
{
    extern __shared__ float sm[];
    float* ys = sm;               // [64 n][65] : ys[n][k]
    float* ws = ys + 64 * 65;     // [64 k][132]: ws[k][c]
    const int b  = blockIdx.y;
    const int n0 = blockIdx.x * 64;
    const int tid = threadIdx.x;

    const float* yg = g_y + (size_t)(b * NPOS + n0) * CB;
    for (int idx = tid; idx < 64 * 64; idx += 256) {
        int n = idx >> 6, k = idx & 63;
        ys[n * 65 + k] = yg[idx];
    }
    for (int i = tid; i < CIN * CB; i += 256) {
        int c = i >> 6, k = i & 63;
        ws[k * 132 + c] = wl[i];
    }
    __syncthreads();

    const int n  = tid & 63;
    const int cb = (tid >> 6) * 32;
    unsigned long long acc2[16];
#pragma unroll
    for (int i = 0; i < 16; i++) acc2[i] = 0ull;

    for (int k = 0; k < CB; k++) {
        float yv = ys[n * 65 + k];
        unsigned long long yp = pk2(yv, yv);
        const double2* wr = (const double2*)(ws + k * 132 + cb);
#pragma unroll
        for (int q = 0; q < 8; q++) {
            double2 wv = wr[q];
            fma2(acc2[2*q],   __double_as_longlong(wv.x), yp);
            fma2(acc2[2*q+1], __double_as_longlong(wv.y), yp);
        }
    }
#pragma unroll
    for (int q = 0; q < 16; q++) {
        float2 t = upk2(acc2[q]);
        int o0 = (b * CIN + cb + 2 * q) * NPOS + n0 + n;
        out[o0]        = t.x + x[o0];
        out[o0 + NPOS] = t.y + x[o0 + NPOS];
    }
}

// ---------------------------------------------------------------------------
extern "C" void kernel_launch(void* const* d_in, const int* in_sizes, int n_in,
                              void* d_out, int out_size)
{
    const float* x  = (const float*)d_in[0];
    const float* wt = (const float*)d_in[1];
    const float* wp = (const float*)d_in[2];
    const float* wg = (const float*)d_in[3];
    const float* wl = (const float*)d_in[4];
    float* out = (float*)d_out;

    int smem1 = (CIN * 64 + 3 * CIN * 65) * (int)sizeof(float);        // 132,608 B
    int smem2 = (2 * 128 * SH + 2 * KVSZ) * (int)sizeof(__half);       //  92,160 B
    int smem3 = (64 * 65 + 64 * 132) * (int)sizeof(float);             //  50,432 B
    cudaFuncSetAttribute(proj_kernel, cudaFuncAttributeMaxDynamicSharedMemorySize, smem1);
    cudaFuncSetAttribute(attn_kernel, cudaFuncAttributeMaxDynamicSharedMemorySize, smem2);
    cudaFuncSetAttribute(out_kernel,  cudaFuncAttributeMaxDynamicSharedMemorySize, smem3);

    dim3 grid1(NPOS / 64, NB);
    dim3 grid2(NPOS / 128, NB);
    proj_kernel<<<grid1, 256, smem1>>>(x, wt, wp, wg);
    attn_kernel<<<grid2, 128, smem2>>>();
    out_kernel<<<grid1, 256, smem3>>>(x, wl, out);
}

// round 8
// speedup vs baseline: 4.6929x; 1.0880x over previous
#include <cuda_runtime.h>
#include <cuda_fp16.h>
#include <math.h>
#include <stdint.h>

#define NB   8
#define CIN  128
#define CB   64
#define NPOS 4096
#define SH   72   // smem stride (halves): conflict-free frags/LDSM
#define LOG2E 1.4426950408889634f

// fp16 operands, pre-converted by proj: [b][n][64] (hi/lo) ; vt: [b][d][n]
// NOTE: g_qh/g_ql hold theta PRE-SCALED by log2(e)  -> softmax uses exp2.
__device__ __align__(16) __half g_qh[NB * NPOS * CB];
__device__ __align__(16) __half g_ql[NB * NPOS * CB];
__device__ __align__(16) __half g_kh[NB * NPOS * CB];
__device__ __align__(16) __half g_kl[NB * NPOS * CB];
__device__ __align__(16) __half g_vt[NB * CB * NPOS];

// ---- helpers ---------------------------------------------------------------
__device__ __forceinline__ float ex2(float x) {
    float y;
    asm("ex2.approx.ftz.f32 %0, %1;" : "=f"(y) : "f"(x));
    return y;
}
__device__ __forceinline__ void cpasync16(uint32_t saddr, const void* g) {
    asm volatile("cp.async.ca.shared.global [%0], [%1], 16;"
                 :: "r"(saddr), "l"(g) : "memory");
}
#define CP_COMMIT() asm volatile("cp.async.commit_group;" ::: "memory")
#define CP_WAIT0()  asm volatile("cp.async.wait_group 0;" ::: "memory")

// ---------------------------------------------------------------------------
// Kernel 1: theta/phi/g = W @ x (smem-staged scalar FFMA). Epilogue emits
// fp16 hi/lo q (x log2e), k, and v transposed via smem (coalesced 16B STG).
// ---------------------------------------------------------------------------
__global__ void __launch_bounds__(256) proj_kernel(
    const float* __restrict__ x, const float* __restrict__ wt,
    const float* __restrict__ wp, const float* __restrict__ wg)
{
    extern __shared__ float sm[];
    float* xs = sm;               // [128][64]   xs[c][n]
    float* ws = sm + CIN * 64;    // 3 x [128][65], transposed: ws[c][k]
    const int b  = blockIdx.y;
    const int n0 = blockIdx.x * 64;
    const int tid = threadIdx.x;

    for (int i = tid; i < CIN * 64; i += 256) {
        int c = i >> 6, j = i & 63;
        xs[i] = x[(b * CIN + c) * NPOS + n0 + j];
    }
    for (int i = tid; i < CB * CIN; i += 256) {
        int k = i >> 7, c = i & 127;
        ws[c * 65 + k]                = wt[i];
        ws[CIN * 65 + c * 65 + k]     = wp[i];
        ws[2 * CIN * 65 + c * 65 + k] = wg[i];
    }
    __syncthreads();

    const int k  = tid & 63;
    const int nb = (tid >> 6) * 16;
    float at[16], ap[16], ag[16];
#pragma unroll
    for (int i = 0; i < 16; i++) { at[i] = 0.f; ap[i] = 0.f; ag[i] = 0.f; }

    for (int c = 0; c < CIN; c++) {
        float w0 = ws[c * 65 + k];
        float w1 = ws[CIN * 65 + c * 65 + k];
        float w2 = ws[2 * CIN * 65 + c * 65 + k];
        const float4* xr = (const float4*)(xs + c * 64 + nb);
#pragma unroll
        for (int q = 0; q < 4; q++) {
            float4 xv = xr[q];
            at[4*q+0] += w0 * xv.x; at[4*q+1] += w0 * xv.y;
            at[4*q+2] += w0 * xv.z; at[4*q+3] += w0 * xv.w;
            ap[4*q+0] += w1 * xv.x; ap[4*q+1] += w1 * xv.y;
            ap[4*q+2] += w1 * xv.z; ap[4*q+3] += w1 * xv.w;
            ag[4*q+0] += w2 * xv.x; ag[4*q+1] += w2 * xv.y;
            ag[4*q+2] += w2 * xv.z; ag[4*q+3] += w2 * xv.w;
        }
    }

#pragma unroll
    for (int i = 0; i < 16; i++) {
        int n = n0 + nb + i;
        int o = (b * NPOS + n) * CB + k;
        float tq = at[i] * LOG2E;           // base-2 softmax pre-scale
        __half th = __float2half_rn(tq);
        g_qh[o] = th;
        g_ql[o] = __float2half_rn(tq - __half2float(th));
        float tk = ap[i];
        __half kh = __float2half_rn(tk);
        g_kh[o] = kh;
        g_kl[o] = __float2half_rn(tk - __half2float(kh));
    }

    // v: transpose through smem, then coalesced 16B row writes
    __syncthreads();
    __half* vs = (__half*)sm;              // [64 k][72]
#pragma unroll
    for (int i = 0; i < 16; i++)
        vs[k * SH + nb + i] = __float2half_rn(ag[i]);
    __syncthreads();
#pragma unroll
    for (int it = 0; it < 2; it++) {
        int ch = tid + it * 256;
        int kk = ch >> 3, cc = ch & 7;
        *(uint4*)(g_vt + ((size_t)b * CB + kk) * NPOS + n0 + cc * 8) =
            *(const uint4*)(vs + kk * SH + cc * 8);
    }
}

// ---------------------------------------------------------------------------
// Kernel 2: flash attention + FUSED final projection & residual.
// mma.sync m16n8k16 fp16/fp32, hi/lo logit split, ldmatrix frags, cp.async
// double-buffered K/V. Epilogue: out = w_last @ y + x via 3-term HMMA.
// ---------------------------------------------------------------------------
#define MMA16816(C, A0, A1, A2, A3, B0, B1)                                   \
    asm volatile("mma.sync.aligned.m16n8k16.row.col.f32.f16.f16.f32 "         \
                 "{%0,%1,%2,%3}, {%4,%5,%6,%7}, {%8,%9}, {%0,%1,%2,%3};"      \
                 : "+f"(C[0]), "+f"(C[1]), "+f"(C[2]), "+f"(C[3])             \
                 : "r"(A0), "r"(A1), "r"(A2), "r"(A3), "r"(B0), "r"(B1))

#define LDSM4(R0, R1, R2, R3, ADDR)                                           \
    asm volatile("ldmatrix.sync.aligned.m8n8.x4.shared.b16 {%0,%1,%2,%3}, [%4];" \
                 : "=r"(R0), "=r"(R1), "=r"(R2), "=r"(R3) : "r"(ADDR))

__device__ __forceinline__ uint32_t pack_h2(float a, float b) {
    __half2 h = __floats2half2_rn(a, b);
    return *(uint32_t*)&h;
}

// smem (halves): Qh[128*SH] | Ql[128*SH] | 2 x { Kh[64*SH] | Kl[64*SH] | Vt[64*SH] }
// epilogue overlay: y_hi -> Qh region, y_lo -> Ql region, w_hi/w_lo -> KV region
#define OQ_H  0
#define OQ_L  (128 * SH)
#define OKV   (2 * 128 * SH)
#define KVSZ  (3 * 64 * SH)
#define OK_L  (64 * SH)
#define OV_T  (2 * 64 * SH)
#define OW_L  (OKV + 128 * SH)

__global__ void __launch_bounds__(128, 2) attn_kernel(
    const float* __restrict__ wlast, const float* __restrict__ xg,
    float* __restrict__ outg)
{
    extern __shared__ __half hsm[];
    const int b   = blockIdx.y;
    const int n0  = blockIdx.x * 128;
    const int tid = threadIdx.x;
    const int w    = tid >> 5;
    const int lane = tid & 31;
    const int g8   = lane >> 2;
    const int qd   = lane & 3;

    const uint32_t sbase = (uint32_t)__cvta_generic_to_shared(hsm);
    const uint32_t qoff = (uint32_t)(((lane & 15) * SH + ((lane & 16) >> 1)) * 2);
    const uint32_t koff = (uint32_t)((((lane & 7) + ((lane & 16) >> 1)) * SH + (lane & 8)) * 2);

    const __half* khg_b = g_kh + (size_t)b * NPOS * CB;
    const __half* klg_b = g_kl + (size_t)b * NPOS * CB;
    const __half* vtg_b = g_vt + (size_t)b * CB * NPOS;

    const int r0 = tid >> 3;
    const int c0 = tid & 7;

    // ---- prologue: issue kb=0 into buf 0 ----
    {
        uint32_t skv = sbase + OKV * 2;
#pragma unroll
        for (int i = 0; i < 4; i++) {
            int r = r0 + i * 16;
            cpasync16(skv + (r * SH + c0 * 8) * 2,        khg_b + r * CB + c0 * 8);
            cpasync16(skv + (OK_L + r * SH + c0 * 8) * 2, klg_b + r * CB + c0 * 8);
            cpasync16(skv + (OV_T + r * SH + c0 * 8) * 2, vtg_b + (size_t)r * NPOS + c0 * 8);
        }
    }
    CP_COMMIT();

    // ---- stage Q (128 rows, hi+lo) ----
    {
        const uint4* qh4 = (const uint4*)(g_qh + (size_t)(b * NPOS + n0) * CB);
        const uint4* ql4 = (const uint4*)(g_ql + (size_t)(b * NPOS + n0) * CB);
#pragma unroll
        for (int i = 0; i < 8; i++) {
            int ch = tid + i * 128;
            int r = ch >> 3, cc = ch & 7;
            *(uint4*)(hsm + OQ_H + r * SH + cc * 8) = qh4[r * 8 + cc];
            *(uint4*)(hsm + OQ_L + r * SH + cc * 8) = ql4[r * 8 + cc];
        }
    }

    float m01[2][2], l01[2][2];
#pragma unroll
    for (int h = 0; h < 2; h++) {
        m01[h][0] = m01[h][1] = -INFINITY;
        l01[h][0] = l01[h][1] = 0.f;
    }
    float o[2][8][4];
#pragma unroll
    for (int h = 0; h < 2; h++)
#pragma unroll
        for (int dt = 0; dt < 8; dt++)
#pragma unroll
            for (int i = 0; i < 4; i++) o[h][dt][i] = 0.f;

    for (int kb = 0; kb < NPOS / 64; kb++) {
        const int p = kb & 1;
        CP_WAIT0();
        __syncthreads();

        if (kb + 1 < NPOS / 64) {
            const __half* khg = khg_b + (size_t)(kb + 1) * 64 * CB;
            const __half* klg = klg_b + (size_t)(kb + 1) * 64 * CB;
            const __half* vtg = vtg_b + (size_t)(kb + 1) * 64;
            uint32_t skv = sbase + (OKV + (p ^ 1) * KVSZ) * 2;
#pragma unroll
            for (int i = 0; i < 4; i++) {
                int r = r0 + i * 16;
                cpasync16(skv + (r * SH + c0 * 8) * 2,        khg + r * CB + c0 * 8);
                cpasync16(skv + (OK_L + r * SH + c0 * 8) * 2, klg + r * CB + c0 * 8);
                cpasync16(skv + (OV_T + r * SH + c0 * 8) * 2, vtg + (size_t)r * NPOS + c0 * 8);
            }
        }
        CP_COMMIT();

        const uint32_t sKh = sbase + (OKV + p * KVSZ) * 2;
        const uint32_t sKl = sKh + OK_L * 2;
        const uint32_t sVt = sKh + OV_T * 2;

        // ---- S = Q K^T (both tiles); LDSM fragment loads ----
        float sc[2][8][4];
#pragma unroll
        for (int h = 0; h < 2; h++)
#pragma unroll
            for (int nt = 0; nt < 8; nt++)
#pragma unroll
                for (int i = 0; i < 4; i++) sc[h][nt][i] = 0.f;

#pragma unroll
        for (int ks = 0; ks < 4; ks++) {
            uint32_t a[2][4], e[2][4];
#pragma unroll
            for (int h = 0; h < 2; h++) {
                uint32_t qa = sbase + (OQ_H + (w * 32 + h * 16) * SH + ks * 16) * 2 + qoff;
                uint32_t la = sbase + (OQ_L + (w * 32 + h * 16) * SH + ks * 16) * 2 + qoff;
                LDSM4(a[h][0], a[h][1], a[h][2], a[h][3], qa);
                LDSM4(e[h][0], e[h][1], e[h][2], e[h][3], la);
            }
#pragma unroll
            for (int ntp = 0; ntp < 4; ntp++) {
                uint32_t kh0, kh1, kh2, kh3, kl0, kl1, kl2, kl3;
                uint32_t ka = sKh + (ntp * 16 * SH + ks * 16) * 2 + koff;
                uint32_t lb = sKl + (ntp * 16 * SH + ks * 16) * 2 + koff;
                LDSM4(kh0, kh1, kh2, kh3, ka);
                LDSM4(kl0, kl1, kl2, kl3, lb);
#pragma unroll
                for (int h = 0; h < 2; h++) {
                    MMA16816(sc[h][2*ntp],   a[h][0], a[h][1], a[h][2], a[h][3], kh0, kh1);
                    MMA16816(sc[h][2*ntp],   a[h][0], a[h][1], a[h][2], a[h][3], kl0, kl1);
                    MMA16816(sc[h][2*ntp],   e[h][0], e[h][1], e[h][2], e[h][3], kh0, kh1);
                    MMA16816(sc[h][2*ntp+1], a[h][0], a[h][1], a[h][2], a[h][3], kh2, kh3);
                    MMA16816(sc[h][2*ntp+1], a[h][0], a[h][1], a[h][2], a[h][3], kl2, kl3);
                    MMA16816(sc[h][2*ntp+1], e[h][0], e[h][1], e[h][2], e[h][3], kh2, kh3);
                }
            }
        }

        // ---- online softmax in base 2 ----
#pragma unroll
        for (int h = 0; h < 2; h++) {
            float mx0 = -INFINITY, mx1 = -INFINITY;
#pragma unroll
            for (int nt = 0; nt < 8; nt++) {
                mx0 = fmaxf(mx0, fmaxf(sc[h][nt][0], sc[h][nt][1]));
                mx1 = fmaxf(mx1, fmaxf(sc[h][nt][2], sc[h][nt][3]));
            }
#pragma unroll
            for (int off = 1; off <= 2; off <<= 1) {
                mx0 = fmaxf(mx0, __shfl_xor_sync(0xffffffffu, mx0, off));
                mx1 = fmaxf(mx1, __shfl_xor_sync(0xffffffffu, mx1, off));
            }
            float mn0 = fmaxf(m01[h][0], mx0);
            float mn1 = fmaxf(m01[h][1], mx1);
            float s0 = ex2(m01[h][0] - mn0);
            float s1 = ex2(m01[h][1] - mn1);
            float rs0 = 0.f, rs1 = 0.f;
#pragma unroll
            for (int nt = 0; nt < 8; nt++) {
                sc[h][nt][0] = ex2(sc[h][nt][0] - mn0);
                sc[h][nt][1] = ex2(sc[h][nt][1] - mn0);
                sc[h][nt][2] = ex2(sc[h][nt][2] - mn1);
                sc[h][nt][3] = ex2(sc[h][nt][3] - mn1);
                rs0 += sc[h][nt][0] + sc[h][nt][1];
                rs1 += sc[h][nt][2] + sc[h][nt][3];
            }
#pragma unroll
            for (int off = 1; off <= 2; off <<= 1) {
                rs0 += __shfl_xor_sync(0xffffffffu, rs0, off);
                rs1 += __shfl_xor_sync(0xffffffffu, rs1, off);
            }
            l01[h][0] = l01[h][0] * s0 + rs0;  m01[h][0] = mn0;
            l01[h][1] = l01[h][1] * s1 + rs1;  m01[h][1] = mn1;
#pragma unroll
            for (int dt = 0; dt < 8; dt++) {
                o[h][dt][0] *= s0; o[h][dt][1] *= s0;
                o[h][dt][2] *= s1; o[h][dt][3] *= s1;
            }
        }

        // ---- O += P V ----
#pragma unroll
        for (int kc = 0; kc < 4; kc++) {
            uint32_t pa[2][4];
#pragma unroll
            for (int h = 0; h < 2; h++) {
                pa[h][0] = pack_h2(sc[h][2*kc][0],   sc[h][2*kc][1]);
                pa[h][1] = pack_h2(sc[h][2*kc][2],   sc[h][2*kc][3]);
                pa[h][2] = pack_h2(sc[h][2*kc+1][0], sc[h][2*kc+1][1]);
                pa[h][3] = pack_h2(sc[h][2*kc+1][2], sc[h][2*kc+1][3]);
            }
#pragma unroll
            for (int dtp = 0; dtp < 4; dtp++) {
                uint32_t v0, v1, v2, v3;
                uint32_t va = sVt + (dtp * 16 * SH + kc * 16) * 2 + koff;
                LDSM4(v0, v1, v2, v3, va);
#pragma unroll
                for (int h = 0; h < 2; h++) {
                    MMA16816(o[h][2*dtp],   pa[h][0], pa[h][1], pa[h][2], pa[h][3], v0, v1);
                    MMA16816(o[h][2*dtp+1], pa[h][0], pa[h][1], pa[h][2], pa[h][3], v2, v3);
                }
            }
        }
    }

    // ===== fused epilogue: out = w_last @ y + x =====
    __syncthreads();   // everyone done with Q and K/V smem

    // stage normalized y (hi/lo) into Q region: ys[n-row][k]
    __half* ysh = hsm + OQ_H;
    __half* ysl = hsm + OQ_L;
#pragma unroll
    for (int h = 0; h < 2; h++) {
        float inv0 = 1.f / l01[h][0], inv1 = 1.f / l01[h][1];
        int r = w * 32 + h * 16 + g8;
#pragma unroll
        for (int dt = 0; dt < 8; dt++) {
            int d = dt * 8 + 2 * qd;
            float y0 = o[h][dt][0] * inv0, y1 = o[h][dt][1] * inv0;
            float y2 = o[h][dt][2] * inv1, y3 = o[h][dt][3] * inv1;
            __half a0 = __float2half_rn(y0), a1 = __float2half_rn(y1);
            __half a2 = __float2half_rn(y2), a3 = __float2half_rn(y3);
            ysh[r * SH + d]           = a0;
            ysh[r * SH + d + 1]       = a1;
            ysh[(r + 8) * SH + d]     = a2;
            ysh[(r + 8) * SH + d + 1] = a3;
            ysl[r * SH + d]           = __float2half_rn(y0 - __half2float(a0));
            ysl[r * SH + d + 1]       = __float2half_rn(y1 - __half2float(a1));
            ysl[(r + 8) * SH + d]     = __float2half_rn(y2 - __half2float(a2));
            ysl[(r + 8) * SH + d + 1] = __float2half_rn(y3 - __half2float(a3));
        }
    }
    // stage w_last (hi/lo) into KV region: ws[c-row][k]; thread tid -> row c=tid
    {
        __half* wsh = hsm + OKV;
        __half* wsl = hsm + OW_L;
        const float4* wr = (const float4*)(wlast + tid * CB);
#pragma unroll
        for (int k4 = 0; k4 < 16; k4++) {
            float4 wv = wr[k4];
            float vv[4] = {wv.x, wv.y, wv.z, wv.w};
#pragma unroll
            for (int j = 0; j < 4; j++) {
                __half hh = __float2half_rn(vv[j]);
                wsh[tid * SH + k4 * 4 + j] = hh;
                wsl[tid * SH + k4 * 4 + j] = __float2half_rn(vv[j] - __half2float(hh));
            }
        }
    }
    __syncthreads();

    // GEMM: out[c, n] ; warp covers c = w*32..w*32+31, all 128 n in 4 chunks
#pragma unroll
    for (int nc = 0; nc < 4; nc++) {
        float acc[2][4][4];
#pragma unroll
        for (int ct = 0; ct < 2; ct++)
#pragma unroll
            for (int nt = 0; nt < 4; nt++)
#pragma unroll
                for (int i = 0; i < 4; i++) acc[ct][nt][i] = 0.f;

#pragma unroll
        for (int ks = 0; ks < 4; ks++) {
            uint32_t ah[2][4], al[2][4];
#pragma unroll
            for (int ct = 0; ct < 2; ct++) {
                uint32_t wa = sbase + (OKV + (w * 32 + ct * 16) * SH + ks * 16) * 2 + qoff;
                uint32_t wb = sbase + (OW_L + (w * 32 + ct * 16) * SH + ks * 16) * 2 + qoff;
                LDSM4(ah[ct][0], ah[ct][1], ah[ct][2], ah[ct][3], wa);
                LDSM4(al[ct][0], al[ct][1], al[ct][2], al[ct][3], wb);
            }
#pragma unroll
            for (int ntp = 0; ntp < 2; ntp++) {
                uint32_t bh0, bh1, bh2, bh3, bl0, bl1, bl2, bl3;
                uint32_t ba = sbase + (OQ_H + (nc * 32 + ntp * 16) * SH + ks * 16) * 2 + koff;
                uint32_t bb = sbase + (OQ_L + (nc * 32 + ntp * 16) * SH + ks * 16) * 2 + koff;
                LDSM4(bh0, bh1, bh2, bh3, ba);
                LDSM4(bl0, bl1, bl2, bl3, bb);
#pragma unroll
                for (int ct = 0; ct < 2; ct++) {
                    MMA16816(acc[ct][2*ntp],   ah[ct][0], ah[ct][1], ah[ct][2], ah[ct][3], bh0, bh1);
                    MMA16816(acc[ct][2*ntp],   ah[ct][0], ah[ct][1], ah[ct][2], ah[ct][3], bl0, bl1);
                    MMA16816(acc[ct][2*ntp],   al[ct][0], al[ct][1], al[ct][2], al[ct][3], bh0, bh1);
                    MMA16816(acc[ct][2*ntp+1], ah[ct][0], ah[ct][1], ah[ct][2], ah[ct][3], bh2, bh3);
                    MMA16816(acc[ct][2*ntp+1], ah[ct][0], ah[ct][1], ah[ct][2], ah[ct][3], bl2, bl3);
                    MMA16816(acc[ct][2*ntp+1], al[ct][0], al[ct][1], al[ct][2], al[ct][3], bh2, bh3);
                }
            }
        }

        // residual add + store
#pragma unroll
        for (int ct = 0; ct < 2; ct++) {
            int cr = w * 32 + ct * 16 + g8;
#pragma unroll
            for (int nt = 0; nt < 4; nt++) {
                int n = n0 + nc * 32 + nt * 8 + 2 * qd;
                size_t o0 = ((size_t)b * CIN + cr) * NPOS + n;
                size_t o1 = ((size_t)b * CIN + cr + 8) * NPOS + n;
                float2 x0 = *(const float2*)&xg[o0];
                float2 x1 = *(const float2*)&xg[o1];
                *(float2*)&outg[o0] =
                    make_float2(acc[ct][nt][0] + x0.x, acc[ct][nt][1] + x0.y);
                *(float2*)&outg[o1] =
                    make_float2(acc[ct][nt][2] + x1.x, acc[ct][nt][3] + x1.y);
            }
        }
    }
}

// ---------------------------------------------------------------------------
extern "C" void kernel_launch(void* const* d_in, const int* in_sizes, int n_in,
                              void* d_out, int out_size)
{
    const float* x  = (const float*)d_in[0];
    const float* wt = (const float*)d_in[1];
    const float* wp = (const float*)d_in[2];
    const float* wg = (const float*)d_in[3];
    const float* wl = (const float*)d_in[4];
    float* out = (float*)d_out;

    int smem1 = (CIN * 64 + 3 * CIN * 65) * (int)sizeof(float);        // 132,608 B
    int smem2 = (2 * 128 * SH + 2 * KVSZ) * (int)sizeof(__half);       //  92,160 B
    cudaFuncSetAttribute(proj_kernel, cudaFuncAttributeMaxDynamicSharedMemorySize, smem1);
    cudaFuncSetAttribute(attn_kernel, cudaFuncAttributeMaxDynamicSharedMemorySize, smem2);

    dim3 grid1(NPOS / 64, NB);
    dim3 grid2(NPOS / 128, NB);
    proj_kernel<<<grid1, 256, smem1>>>(x, wt, wp, wg);
    attn_kernel<<<grid2, 128, smem2>>>(wl, x, out);
}